// round 1
// baseline (speedup 1.0000x reference)
#include <cuda_runtime.h>

#define NB 4096
#define NS 10

// ---------------- device scratch (zero-initialized at module load; padding
// columns are never written, so they stay zero across graph replays) --------
__device__ float g_h0[NB * 3072];  // feat(2970)+x_train(95)=3065, padded to 3072
__device__ float g_h1[NB * 1504];  // 1500 padded to 1504
__device__ float g_h2[NB * 800];
__device__ float g_h3[NB * 112];   // 100 padded to 112
__device__ float g_h4[NB * 20];

// ---------------------------------------------------------------------------
// Fused conv stack: one block per batch element. All intermediates in SMEM.
// Layout of every activation buffer: [(c*L + t)*10 + s]
// ---------------------------------------------------------------------------

__device__ __forceinline__ void copy_smem(float* dst, const float* __restrict__ src,
                                          int n, int tid) {
    for (int i = tid; i < n; i += 256) dst[i] = src[i];
}

template <int CIN, int COUT, int L>
__device__ __forceinline__ void conv_layer(const float* __restrict__ in,
                                           float* __restrict__ out,
                                           const float* __restrict__ W,
                                           const float* __restrict__ Bias,
                                           int tid) {
    constexpr int NCH = (L + 7) / 8;
    constexpr int ITEMS = COUT * NS * NCH;
    for (int it = tid; it < ITEMS; it += 256) {
        int co = it / (NS * NCH);
        int r  = it - co * (NS * NCH);
        int s  = r / NCH;
        int tc = r - s * NCH;
        int t0 = tc * 8;

        float bv = Bias[s * COUT + co];
        float acc[8];
#pragma unroll
        for (int j = 0; j < 8; j++) acc[j] = bv;

#pragma unroll
        for (int ci = 0; ci < CIN; ci++) {
            float win[12];
#pragma unroll
            for (int j = 0; j < 12; j++) {
                int t = t0 + j - 2;
                win[j] = (t >= 0 && t < L) ? in[(ci * L + t) * NS + s] : 0.f;
            }
            const float* w = &W[((s * COUT + co) * CIN + ci) * 5];
            float w0 = w[0], w1 = w[1], w2 = w[2], w3 = w[3], w4 = w[4];
#pragma unroll
            for (int j = 0; j < 8; j++)
                acc[j] += w0 * win[j] + w1 * win[j + 1] + w2 * win[j + 2] +
                          w3 * win[j + 3] + w4 * win[j + 4];
        }
#pragma unroll
        for (int j = 0; j < 8; j++) {
            int t = t0 + j;
            if (t < L) out[(co * L + t) * NS + s] = fmaxf(acc[j], 0.f);
        }
    }
}

template <int C, int LIN>
__device__ __forceinline__ void maxpool(const float* __restrict__ in,
                                        float* __restrict__ out, int tid) {
    constexpr int LOUT = (LIN - 5) / 2 + 1;
    constexpr int ITEMS = C * LOUT * NS;
    for (int it = tid; it < ITEMS; it += 256) {
        int co = it / (LOUT * NS);
        int r  = it - co * (LOUT * NS);
        int p  = r / NS;
        int s  = r - p * NS;
        const float* base = &in[(co * LIN + 2 * p) * NS + s];
        float m = fmaxf(fmaxf(fmaxf(base[0], base[NS]),
                              fmaxf(base[2 * NS], base[3 * NS])),
                        base[4 * NS]);
        out[(co * LOUT + p) * NS + s] = m;
    }
}

// smem layout: wbuf[5060] | bufA[8190] | bufB[11850]
#define CONV_SMEM_FLOATS (5060 + 8190 + 11850)

__global__ void __launch_bounds__(256) conv_kernel(
    const float* __restrict__ meteo, const float* __restrict__ x_train,
    const float* __restrict__ cw1, const float* __restrict__ cb1,
    const float* __restrict__ cw2, const float* __restrict__ cb2,
    const float* __restrict__ cw3, const float* __restrict__ cb3,
    const float* __restrict__ cw4, const float* __restrict__ cb4,
    const float* __restrict__ cw5, const float* __restrict__ cb5,
    const float* __restrict__ cw6, const float* __restrict__ cb6) {
    extern __shared__ float sm[];
    float* wb   = sm;
    float* bufA = sm + 5060;
    float* bufB = bufA + 8190;

    int b   = blockIdx.x;
    int tid = threadIdx.x;

    // input (B,237,10) -> bufB (cin=1 layout is identical, contiguous 2370)
    copy_smem(bufB, meteo + b * 2370, 2370, tid);
    copy_smem(wb, cw1, 150, tid);
    copy_smem(wb + 150, cb1, 30, tid);
    __syncthreads();
    conv_layer<1, 3, 237>(bufB, bufA, wb, wb + 150, tid);
    __syncthreads();

    copy_smem(wb, cw2, 750, tid);
    copy_smem(wb + 750, cb2, 50, tid);
    __syncthreads();
    conv_layer<3, 5, 237>(bufA, bufB, wb, wb + 750, tid);
    __syncthreads();

    maxpool<5, 237>(bufB, bufA, tid);  // -> 5 x 117
    copy_smem(wb, cw3, 1750, tid);
    copy_smem(wb + 1750, cb3, 70, tid);
    __syncthreads();
    conv_layer<5, 7, 117>(bufA, bufB, wb, wb + 1750, tid);
    __syncthreads();

    copy_smem(wb, cw4, 2450, tid);
    copy_smem(wb + 2450, cb4, 70, tid);
    __syncthreads();
    conv_layer<7, 7, 117>(bufB, bufA, wb, wb + 2450, tid);
    __syncthreads();

    maxpool<7, 117>(bufA, bufB, tid);  // -> 7 x 57
    copy_smem(wb, cw5, 3150, tid);
    copy_smem(wb + 3150, cb5, 90, tid);
    __syncthreads();
    conv_layer<7, 9, 57>(bufB, bufA, wb, wb + 3150, tid);
    __syncthreads();

    copy_smem(wb, cw6, 4950, tid);
    copy_smem(wb + 4950, cb6, 110, tid);
    __syncthreads();
    conv_layer<9, 11, 57>(bufA, bufB, wb, wb + 4950, tid);
    __syncthreads();

    // maxpool3 (11 x 57 -> 11 x 27) straight into g_h0 + concat x_train
    for (int it = tid; it < 11 * 27 * NS; it += 256) {
        int co = it / (27 * NS);
        int r  = it - co * (27 * NS);
        int p  = r / NS;
        int s  = r - p * NS;
        const float* base = &bufB[(co * 57 + 2 * p) * NS + s];
        float m = fmaxf(fmaxf(fmaxf(base[0], base[NS]),
                              fmaxf(base[2 * NS], base[3 * NS])),
                        base[4 * NS]);
        g_h0[b * 3072 + it] = m;  // it == (co*27+p)*10+s == flatten order
    }
    for (int i = tid; i < 95; i += 256)
        g_h0[b * 3072 + 2970 + i] = x_train[b * 95 + i];
}

// ---------------------------------------------------------------------------
// Tiled fp32 GEMM: C[M,N] = relu(A[M,K] @ B[K,N] + bias)
// BM=BN=128, BK=16, 256 threads, 8x8 microtile. A is padded to KP columns of
// zeros (no K guard on A); M is always a multiple of 128 (no row guard).
// ---------------------------------------------------------------------------
template <bool RELU>
__global__ void __launch_bounds__(256) sgemm_kernel(
    const float* __restrict__ A, const float* __restrict__ B,
    const float* __restrict__ bias, float* __restrict__ C,
    int N, int K, int KP, int lda, int ldb, int ldc) {
    __shared__ float As[16][132];
    __shared__ float Bs[16][128];

    int tid = threadIdx.x;
    int n0  = blockIdx.x * 128;
    int m0  = blockIdx.y * 128;
    int ty  = tid >> 4;         // 0..15
    int tx  = tid & 15;         // 0..15
    int aRow = tid >> 2;        // 0..63
    int aK   = (tid & 3) * 4;   // 0,4,8,12
    int bRow = tid >> 5;        // 0..7
    int bCol = (tid & 31) * 4;  // 0..124

    float acc[8][8];
#pragma unroll
    for (int i = 0; i < 8; i++)
#pragma unroll
        for (int j = 0; j < 8; j++) acc[i][j] = 0.f;

    const float4 z4 = {0.f, 0.f, 0.f, 0.f};
    int nc = n0 + bCol;

    for (int k0 = 0; k0 < KP; k0 += 16) {
        float4 a0 = *(const float4*)&A[(size_t)(m0 + aRow) * lda + k0 + aK];
        float4 a1 = *(const float4*)&A[(size_t)(m0 + aRow + 64) * lda + k0 + aK];
        int kr0 = k0 + bRow, kr1 = k0 + bRow + 8;
        float4 b0 = (kr0 < K && nc < N) ? *(const float4*)&B[(size_t)kr0 * ldb + nc] : z4;
        float4 b1 = (kr1 < K && nc < N) ? *(const float4*)&B[(size_t)kr1 * ldb + nc] : z4;

        __syncthreads();
        As[aK + 0][aRow] = a0.x;  As[aK + 1][aRow] = a0.y;
        As[aK + 2][aRow] = a0.z;  As[aK + 3][aRow] = a0.w;
        As[aK + 0][aRow + 64] = a1.x;  As[aK + 1][aRow + 64] = a1.y;
        As[aK + 2][aRow + 64] = a1.z;  As[aK + 3][aRow + 64] = a1.w;
        *(float4*)&Bs[bRow][bCol]     = b0;
        *(float4*)&Bs[bRow + 8][bCol] = b1;
        __syncthreads();

#pragma unroll
        for (int k = 0; k < 16; k++) {
            float4 aa0 = *(const float4*)&As[k][ty * 4];
            float4 aa1 = *(const float4*)&As[k][64 + ty * 4];
            float4 bb0 = *(const float4*)&Bs[k][tx * 4];
            float4 bb1 = *(const float4*)&Bs[k][64 + tx * 4];
            float ar[8] = {aa0.x, aa0.y, aa0.z, aa0.w, aa1.x, aa1.y, aa1.z, aa1.w};
            float br[8] = {bb0.x, bb0.y, bb0.z, bb0.w, bb1.x, bb1.y, bb1.z, bb1.w};
#pragma unroll
            for (int i = 0; i < 8; i++)
#pragma unroll
                for (int j = 0; j < 8; j++) acc[i][j] += ar[i] * br[j];
        }
    }

    int rows[8], cols[8];
#pragma unroll
    for (int i = 0; i < 4; i++) {
        rows[i]     = m0 + ty * 4 + i;
        rows[i + 4] = m0 + 64 + ty * 4 + i;
        cols[i]     = n0 + tx * 4 + i;
        cols[i + 4] = n0 + 64 + tx * 4 + i;
    }
#pragma unroll
    for (int j = 0; j < 8; j++) {
        if (cols[j] < N) {
            float bv = bias[cols[j]];
#pragma unroll
            for (int i = 0; i < 8; i++) {
                float v = acc[i][j] + bv;
                if (RELU) v = fmaxf(v, 0.f);
                C[(size_t)rows[i] * ldc + cols[j]] = v;
            }
        }
    }
}

// ---------------------------------------------------------------------------
// Final: out[b] = sum_{i<20} h4[b,i]*Wc[i] + xg[b]*Wc[20] + bc
// ---------------------------------------------------------------------------
__global__ void __launch_bounds__(256) final_kernel(
    const float* __restrict__ h4, const float* __restrict__ xg,
    const float* __restrict__ Wc, const float* __restrict__ bc,
    float* __restrict__ out) {
    int b = blockIdx.x * blockDim.x + threadIdx.x;
    if (b < NB) {
        float acc = bc[0] + xg[b] * Wc[20];
#pragma unroll
        for (int i = 0; i < 20; i++) acc += h4[b * 20 + i] * Wc[i];
        out[b] = acc;
    }
}

// ---------------------------------------------------------------------------
extern "C" void kernel_launch(void* const* d_in, const int* in_sizes, int n_in,
                              void* d_out, int out_size) {
    const float* x_train = (const float*)d_in[0];
    const float* meteo   = (const float*)d_in[1];
    const float* xg      = (const float*)d_in[2];
    const float* cw[6];
    const float* cb[6];
    for (int l = 0; l < 6; l++) {
        cw[l] = (const float*)d_in[3 + 2 * l];
        cb[l] = (const float*)d_in[4 + 2 * l];
    }
    const float* W1 = (const float*)d_in[15];
    const float* b1 = (const float*)d_in[16];
    const float* W2 = (const float*)d_in[17];
    const float* b2 = (const float*)d_in[18];
    const float* W3 = (const float*)d_in[19];
    const float* b3 = (const float*)d_in[20];
    const float* W4 = (const float*)d_in[21];
    const float* b4 = (const float*)d_in[22];
    const float* Wc = (const float*)d_in[23];
    const float* bc = (const float*)d_in[24];

    float *h0, *h1, *h2, *h3, *h4;
    cudaGetSymbolAddress((void**)&h0, g_h0);
    cudaGetSymbolAddress((void**)&h1, g_h1);
    cudaGetSymbolAddress((void**)&h2, g_h2);
    cudaGetSymbolAddress((void**)&h3, g_h3);
    cudaGetSymbolAddress((void**)&h4, g_h4);

    const int conv_smem = CONV_SMEM_FLOATS * (int)sizeof(float);
    cudaFuncSetAttribute(conv_kernel, cudaFuncAttributeMaxDynamicSharedMemorySize,
                         conv_smem);

    conv_kernel<<<NB, 256, conv_smem>>>(meteo, x_train, cw[0], cb[0], cw[1], cb[1],
                                        cw[2], cb[2], cw[3], cb[3], cw[4], cb[4],
                                        cw[5], cb[5]);

    // L1: 4096x1500, K=3065 (pad 3072)
    sgemm_kernel<true><<<dim3(12, 32), 256>>>(h0, W1, b1, h1, 1500, 3065, 3072,
                                              3072, 1500, 1504);
    // L2: 4096x800, K=1500 (pad 1504)
    sgemm_kernel<true><<<dim3(7, 32), 256>>>(h1, W2, b2, h2, 800, 1500, 1504,
                                             1504, 800, 800);
    // L3: 4096x100, K=800
    sgemm_kernel<true><<<dim3(1, 32), 256>>>(h2, W3, b3, h3, 100, 800, 800,
                                             800, 100, 112);
    // L4: 4096x20, K=100 (pad 112)
    sgemm_kernel<true><<<dim3(1, 32), 256>>>(h3, W4, b4, h4, 20, 100, 112,
                                             112, 20, 20);

    final_kernel<<<NB / 256, 256>>>(h4, xg, Wc, bc, (float*)d_out);
}

// round 4
// speedup vs baseline: 1.4006x; 1.4006x over previous
#include <cuda_runtime.h>
#include <cuda_bf16.h>
#include <cstdint>

#define NB 4096
#define NS 10

// ===========================================================================
// Device scratch (zero-initialized; padding regions never written => stay 0)
// ===========================================================================
__device__ __align__(16) __nv_bfloat16 g_h0hi[NB * 3072];
__device__ __align__(16) __nv_bfloat16 g_h0lo[NB * 3072];
__device__ __align__(16) __nv_bfloat16 g_h1hi[NB * 1536];
__device__ __align__(16) __nv_bfloat16 g_h1lo[NB * 1536];
__device__ __align__(16) __nv_bfloat16 g_h2hi[NB * 896];
__device__ __align__(16) __nv_bfloat16 g_h2lo[NB * 896];
__device__ float g_h3[NB * 100];
// transposed + split weights: [Npad][Kpad]
__device__ __align__(16) __nv_bfloat16 g_w1thi[1536 * 3072];
__device__ __align__(16) __nv_bfloat16 g_w1tlo[1536 * 3072];
__device__ __align__(16) __nv_bfloat16 g_w2thi[896 * 1536];
__device__ __align__(16) __nv_bfloat16 g_w2tlo[896 * 1536];
__device__ __align__(16) __nv_bfloat16 g_w3thi[128 * 896];
__device__ __align__(16) __nv_bfloat16 g_w3tlo[128 * 896];

__device__ __forceinline__ uint32_t smem_u32_of(const void* p) {
    uint32_t a;
    asm("{ .reg .u64 t; cvta.to.shared.u64 t, %1; cvt.u32.u64 %0, t; }"
        : "=r"(a) : "l"(p));
    return a;
}

__device__ __forceinline__ void split_bf16(float v, __nv_bfloat16& hi, __nv_bfloat16& lo) {
    hi = __float2bfloat16(v);
    lo = __float2bfloat16(v - __bfloat162float(hi));
}

// ===========================================================================
// Fused conv stack (validated in round 0/1)
// ===========================================================================
__device__ __forceinline__ void copy_smem(float* dst, const float* __restrict__ src,
                                          int n, int tid) {
    for (int i = tid; i < n; i += 256) dst[i] = src[i];
}

template <int CIN, int COUT, int L>
__device__ __forceinline__ void conv_layer(const float* __restrict__ in,
                                           float* __restrict__ out,
                                           const float* __restrict__ W,
                                           const float* __restrict__ Bias, int tid) {
    constexpr int NCH = (L + 7) / 8;
    constexpr int ITEMS = COUT * NS * NCH;
    for (int it = tid; it < ITEMS; it += 256) {
        int co = it / (NS * NCH);
        int r = it - co * (NS * NCH);
        int s = r / NCH;
        int tc = r - s * NCH;
        int t0 = tc * 8;
        float bv = Bias[s * COUT + co];
        float acc[8];
#pragma unroll
        for (int j = 0; j < 8; j++) acc[j] = bv;
#pragma unroll
        for (int ci = 0; ci < CIN; ci++) {
            float win[12];
#pragma unroll
            for (int j = 0; j < 12; j++) {
                int t = t0 + j - 2;
                win[j] = (t >= 0 && t < L) ? in[(ci * L + t) * NS + s] : 0.f;
            }
            const float* w = &W[((s * COUT + co) * CIN + ci) * 5];
            float w0 = w[0], w1 = w[1], w2 = w[2], w3 = w[3], w4 = w[4];
#pragma unroll
            for (int j = 0; j < 8; j++)
                acc[j] += w0 * win[j] + w1 * win[j + 1] + w2 * win[j + 2] +
                          w3 * win[j + 3] + w4 * win[j + 4];
        }
#pragma unroll
        for (int j = 0; j < 8; j++) {
            int t = t0 + j;
            if (t < L) out[(co * L + t) * NS + s] = fmaxf(acc[j], 0.f);
        }
    }
}

template <int C, int LIN>
__device__ __forceinline__ void maxpool(const float* __restrict__ in,
                                        float* __restrict__ out, int tid) {
    constexpr int LOUT = (LIN - 5) / 2 + 1;
    constexpr int ITEMS = C * LOUT * NS;
    for (int it = tid; it < ITEMS; it += 256) {
        int co = it / (LOUT * NS);
        int r = it - co * (LOUT * NS);
        int p = r / NS;
        int s = r - p * NS;
        const float* base = &in[(co * LIN + 2 * p) * NS + s];
        float m = fmaxf(fmaxf(fmaxf(base[0], base[NS]),
                              fmaxf(base[2 * NS], base[3 * NS])), base[4 * NS]);
        out[(co * LOUT + p) * NS + s] = m;
    }
}

#define CONV_SMEM_FLOATS (5060 + 8190 + 11850)

__global__ void __launch_bounds__(256) conv_kernel(
    const float* __restrict__ meteo, const float* __restrict__ x_train,
    const float* __restrict__ cw1, const float* __restrict__ cb1,
    const float* __restrict__ cw2, const float* __restrict__ cb2,
    const float* __restrict__ cw3, const float* __restrict__ cb3,
    const float* __restrict__ cw4, const float* __restrict__ cb4,
    const float* __restrict__ cw5, const float* __restrict__ cb5,
    const float* __restrict__ cw6, const float* __restrict__ cb6) {
    extern __shared__ float sm[];
    float* wb = sm;
    float* bufA = sm + 5060;
    float* bufB = bufA + 8190;
    int b = blockIdx.x;
    int tid = threadIdx.x;

    copy_smem(bufB, meteo + b * 2370, 2370, tid);
    copy_smem(wb, cw1, 150, tid);
    copy_smem(wb + 150, cb1, 30, tid);
    __syncthreads();
    conv_layer<1, 3, 237>(bufB, bufA, wb, wb + 150, tid);
    __syncthreads();

    copy_smem(wb, cw2, 750, tid);
    copy_smem(wb + 750, cb2, 50, tid);
    __syncthreads();
    conv_layer<3, 5, 237>(bufA, bufB, wb, wb + 750, tid);
    __syncthreads();

    maxpool<5, 237>(bufB, bufA, tid);
    copy_smem(wb, cw3, 1750, tid);
    copy_smem(wb + 1750, cb3, 70, tid);
    __syncthreads();
    conv_layer<5, 7, 117>(bufA, bufB, wb, wb + 1750, tid);
    __syncthreads();

    copy_smem(wb, cw4, 2450, tid);
    copy_smem(wb + 2450, cb4, 70, tid);
    __syncthreads();
    conv_layer<7, 7, 117>(bufB, bufA, wb, wb + 2450, tid);
    __syncthreads();

    maxpool<7, 117>(bufA, bufB, tid);
    copy_smem(wb, cw5, 3150, tid);
    copy_smem(wb + 3150, cb5, 90, tid);
    __syncthreads();
    conv_layer<7, 9, 57>(bufB, bufA, wb, wb + 3150, tid);
    __syncthreads();

    copy_smem(wb, cw6, 4950, tid);
    copy_smem(wb + 4950, cb6, 110, tid);
    __syncthreads();
    conv_layer<9, 11, 57>(bufA, bufB, wb, wb + 4950, tid);
    __syncthreads();

    for (int it = tid; it < 11 * 27 * NS; it += 256) {
        int co = it / (27 * NS);
        int r = it - co * (27 * NS);
        int p = r / NS;
        int s = r - p * NS;
        const float* base = &bufB[(co * 57 + 2 * p) * NS + s];
        float m = fmaxf(fmaxf(fmaxf(base[0], base[NS]),
                              fmaxf(base[2 * NS], base[3 * NS])), base[4 * NS]);
        __nv_bfloat16 hi, lo;
        split_bf16(m, hi, lo);
        g_h0hi[(size_t)b * 3072 + it] = hi;
        g_h0lo[(size_t)b * 3072 + it] = lo;
    }
    for (int i = tid; i < 95; i += 256) {
        __nv_bfloat16 hi, lo;
        split_bf16(x_train[b * 95 + i], hi, lo);
        g_h0hi[(size_t)b * 3072 + 2970 + i] = hi;
        g_h0lo[(size_t)b * 3072 + 2970 + i] = lo;
    }
}

// ===========================================================================
// Weight prep: transpose W[K,N] -> T[n][k] bf16 hi/lo (padding stays zero)
// ===========================================================================
__global__ void __launch_bounds__(256) prep_w(const float* __restrict__ W,
                                              int K, int N, int Kpad,
                                              __nv_bfloat16* __restrict__ Th,
                                              __nv_bfloat16* __restrict__ Tl) {
    __shared__ float sm[32][33];
    int n0 = blockIdx.x * 32, k0 = blockIdx.y * 32;
    int tx = threadIdx.x, ty = threadIdx.y;  // 32 x 8
    for (int i = ty; i < 32; i += 8) {
        int k = k0 + i, n = n0 + tx;
        sm[i][tx] = (k < K && n < N) ? W[(size_t)k * N + n] : 0.f;
    }
    __syncthreads();
    for (int i = ty; i < 32; i += 8) {
        int n = n0 + i, k = k0 + tx;
        if (n < N && k < K) {
            __nv_bfloat16 hi, lo;
            split_bf16(sm[tx][i], hi, lo);
            Th[(size_t)n * Kpad + k] = hi;
            Tl[(size_t)n * Kpad + k] = lo;
        }
    }
}

// ===========================================================================
// bf16 mma.sync GEMM with split-bf16 3-pass accumulation.
//   C[4096, N] = relu(A @ W^T + bias), A:[4096][Kpad] hi/lo, B(W^T):[Npad][Kpad]
// CTA: 128x128, BK=32, 256 thr (8 warps 2Mx4N, warp tile 64x32), cp.async 2-stage.
// smem tile row stride 80B (32 elems + 8 pad) -> ldmatrix conflict-free.
// ===========================================================================
#define RS 80                      // row stride bytes
#define TILE_B (128 * RS)          // 10240
#define STAGE_B (4 * TILE_B)       // 40960: [Ah|Al|Bh|Bl]
#define GEMM_SMEM (2 * STAGE_B)

#define CP_ASYNC(s, g) \
    asm volatile("cp.async.cg.shared.global [%0], [%1], 16;" :: "r"(s), "l"(g) : "memory")
#define CP_COMMIT() asm volatile("cp.async.commit_group;" ::: "memory")
#define CP_WAIT(n)  asm volatile("cp.async.wait_group %0;" :: "n"(n) : "memory")

#define LDMX4(r0, r1, r2, r3, a) \
    asm volatile("ldmatrix.sync.aligned.m8n8.x4.shared.b16 {%0,%1,%2,%3}, [%4];" \
                 : "=r"(r0), "=r"(r1), "=r"(r2), "=r"(r3) : "r"(a))

#define MMA(c, a, b) \
    asm volatile("mma.sync.aligned.m16n8k16.row.col.f32.bf16.bf16.f32 " \
                 "{%0,%1,%2,%3}, {%4,%5,%6,%7}, {%8,%9}, {%0,%1,%2,%3};" \
                 : "+f"((c)[0]), "+f"((c)[1]), "+f"((c)[2]), "+f"((c)[3]) \
                 : "r"((a)[0]), "r"((a)[1]), "r"((a)[2]), "r"((a)[3]), \
                   "r"((b)[0]), "r"((b)[1]))

template <bool OUT_BF16>
__global__ void __launch_bounds__(256, 1) mma_gemm(
    const __nv_bfloat16* __restrict__ Ah, const __nv_bfloat16* __restrict__ Al,
    const __nv_bfloat16* __restrict__ Bh, const __nv_bfloat16* __restrict__ Bl,
    const float* __restrict__ bias, int N, int Kpad,
    __nv_bfloat16* __restrict__ Chi, __nv_bfloat16* __restrict__ Clo,
    float* __restrict__ Cf, int ldc) {
    extern __shared__ __align__(16) char smem[];
    uint32_t su = smem_u32_of(smem);

    int tid = threadIdx.x, wid = tid >> 5, lane = tid & 31;
    int warp_m = wid & 1, warp_n = wid >> 1;
    int m0 = blockIdx.y * 128, n0 = blockIdx.x * 128;
    int nkb = Kpad >> 5;

    // global row bases for the 4 tiles of a stage
    const __nv_bfloat16* gsrc[4] = {Ah + (size_t)m0 * Kpad, Al + (size_t)m0 * Kpad,
                                    Bh + (size_t)n0 * Kpad, Bl + (size_t)n0 * Kpad};
    // cp.async mapping: 512 16B-chunks per tile, 2 per thread
    int c0 = tid * 2, c1 = tid * 2 + 1;
    int r0c = c0 >> 2, f0 = (c0 & 3) * 8;  // row, elem offset (8 bf16 = 16B)
    int r1c = c1 >> 2, f1 = (c1 & 3) * 8;

    auto load_stage = [&](int s, int kbe) {
        uint32_t sb = su + s * STAGE_B;
#pragma unroll
        for (int t = 0; t < 4; ++t) {
            const __nv_bfloat16* g = gsrc[t];
            uint32_t tb = sb + t * TILE_B;
            CP_ASYNC(tb + r0c * RS + f0 * 2, g + (size_t)r0c * Kpad + kbe + f0);
            CP_ASYNC(tb + r1c * RS + f1 * 2, g + (size_t)r1c * Kpad + kbe + f1);
        }
        CP_COMMIT();
    };

    // ldmatrix per-lane base offsets
    int g = lane >> 3, lr = lane & 7;
    uint32_t a_off = (uint32_t)((warp_m * 64 + (g & 1) * 8 + lr) * RS + (g >> 1) * 16);
    uint32_t b_off = (uint32_t)((warp_n * 32 + (g >> 1) * 8 + lr) * RS + (g & 1) * 16);

    float acc[4][4][4];
#pragma unroll
    for (int i = 0; i < 4; i++)
#pragma unroll
        for (int j = 0; j < 4; j++)
#pragma unroll
            for (int e = 0; e < 4; e++) acc[i][j][e] = 0.f;

    load_stage(0, 0);

    for (int kb = 0; kb < nkb; ++kb) {
        if (kb + 1 < nkb) { load_stage((kb + 1) & 1, (kb + 1) * 32); CP_WAIT(1); }
        else              { CP_WAIT(0); }
        __syncthreads();

        uint32_t sb = su + (kb & 1) * STAGE_B;
#pragma unroll
        for (int ks = 0; ks < 2; ++ks) {
            uint32_t ko = ks * 32;  // 16 elems = 32 bytes
            uint32_t ah[4][4], al[4][4], bh[4][2], bl[4][2];
#pragma unroll
            for (int i = 0; i < 4; ++i) {
                uint32_t ad = sb + a_off + ko + i * (16 * RS);
                LDMX4(ah[i][0], ah[i][1], ah[i][2], ah[i][3], ad);
                LDMX4(al[i][0], al[i][1], al[i][2], al[i][3], ad + TILE_B);
            }
#pragma unroll
            for (int j = 0; j < 4; j += 2) {
                uint32_t bd = sb + 2 * TILE_B + b_off + ko + j * (8 * RS);
                LDMX4(bh[j][0], bh[j][1], bh[j + 1][0], bh[j + 1][1], bd);
                LDMX4(bl[j][0], bl[j][1], bl[j + 1][0], bl[j + 1][1], bd + TILE_B);
            }
#pragma unroll
            for (int i = 0; i < 4; ++i)
#pragma unroll
                for (int j = 0; j < 4; ++j) {
                    MMA(acc[i][j], ah[i], bh[j]);
                    MMA(acc[i][j], ah[i], bl[j]);
                    MMA(acc[i][j], al[i], bh[j]);
                }
        }
        __syncthreads();
    }

    // epilogue
    int row_b = m0 + warp_m * 64 + (lane >> 2);
    int col_b = n0 + warp_n * 32 + (lane & 3) * 2;
#pragma unroll
    for (int i = 0; i < 4; ++i)
#pragma unroll
        for (int j = 0; j < 4; ++j) {
            int col = col_b + j * 8;
            if (col < N) {  // N even => col+1 also < N
                float bv0 = bias[col], bv1 = bias[col + 1];
                int r_lo = row_b + i * 16, r_hi = r_lo + 8;
                float v00 = fmaxf(acc[i][j][0] + bv0, 0.f);
                float v01 = fmaxf(acc[i][j][1] + bv1, 0.f);
                float v10 = fmaxf(acc[i][j][2] + bv0, 0.f);
                float v11 = fmaxf(acc[i][j][3] + bv1, 0.f);
                if (OUT_BF16) {
                    __nv_bfloat16 h0, l0, h1, l1;
                    split_bf16(v00, h0, l0); split_bf16(v01, h1, l1);
                    *(__nv_bfloat162*)&Chi[(size_t)r_lo * ldc + col] =
                        __nv_bfloat162(h0, h1);
                    *(__nv_bfloat162*)&Clo[(size_t)r_lo * ldc + col] =
                        __nv_bfloat162(l0, l1);
                    split_bf16(v10, h0, l0); split_bf16(v11, h1, l1);
                    *(__nv_bfloat162*)&Chi[(size_t)r_hi * ldc + col] =
                        __nv_bfloat162(h0, h1);
                    *(__nv_bfloat162*)&Clo[(size_t)r_hi * ldc + col] =
                        __nv_bfloat162(l0, l1);
                } else {
                    Cf[(size_t)r_lo * ldc + col] = v00;
                    Cf[(size_t)r_lo * ldc + col + 1] = v01;
                    Cf[(size_t)r_hi * ldc + col] = v10;
                    Cf[(size_t)r_hi * ldc + col + 1] = v11;
                }
            }
        }
}

// ===========================================================================
// Tail: h4 = relu(h3 @ W4 + b4); out = [h4, xg] @ Wc + bc
// ===========================================================================
__global__ void __launch_bounds__(256) tail_kernel(
    const float* __restrict__ h3, const float* __restrict__ W4,
    const float* __restrict__ b4, const float* __restrict__ xg,
    const float* __restrict__ Wc, const float* __restrict__ bc,
    float* __restrict__ out) {
    __shared__ float w4s[2000];
    __shared__ float b4s[20], wcs[21], bcs[1];
    int tid = threadIdx.x;
    for (int i = tid; i < 2000; i += 256) w4s[i] = W4[i];
    if (tid < 20) b4s[tid] = b4[tid];
    if (tid < 21) wcs[tid] = Wc[tid];
    if (tid == 0) bcs[0] = bc[0];
    __syncthreads();

    int b = blockIdx.x * 256 + tid;
    float acc[20];
#pragma unroll
    for (int j = 0; j < 20; ++j) acc[j] = b4s[j];
    const float* hr = h3 + (size_t)b * 100;
    for (int k = 0; k < 100; ++k) {
        float a = hr[k];
        const float* w = &w4s[k * 20];
#pragma unroll
        for (int j = 0; j < 20; ++j) acc[j] = fmaf(a, w[j], acc[j]);
    }
    float o = bcs[0] + xg[b] * wcs[20];
#pragma unroll
    for (int j = 0; j < 20; ++j) o += fmaxf(acc[j], 0.f) * wcs[j];
    out[b] = o;
}

// ===========================================================================
extern "C" void kernel_launch(void* const* d_in, const int* in_sizes, int n_in,
                              void* d_out, int out_size) {
    const float* x_train = (const float*)d_in[0];
    const float* meteo = (const float*)d_in[1];
    const float* xg = (const float*)d_in[2];
    const float* cw[6];
    const float* cb[6];
    for (int l = 0; l < 6; l++) {
        cw[l] = (const float*)d_in[3 + 2 * l];
        cb[l] = (const float*)d_in[4 + 2 * l];
    }
    const float* W1 = (const float*)d_in[15];
    const float* b1 = (const float*)d_in[16];
    const float* W2 = (const float*)d_in[17];
    const float* b2 = (const float*)d_in[18];
    const float* W3 = (const float*)d_in[19];
    const float* b3 = (const float*)d_in[20];
    const float* W4 = (const float*)d_in[21];
    const float* b4 = (const float*)d_in[22];
    const float* Wc = (const float*)d_in[23];
    const float* bc = (const float*)d_in[24];

    __nv_bfloat16 *h0hi, *h0lo, *h1hi, *h1lo, *h2hi, *h2lo;
    __nv_bfloat16 *w1h, *w1l, *w2h, *w2l, *w3h, *w3l;
    float* h3;
    cudaGetSymbolAddress((void**)&h0hi, g_h0hi);
    cudaGetSymbolAddress((void**)&h0lo, g_h0lo);
    cudaGetSymbolAddress((void**)&h1hi, g_h1hi);
    cudaGetSymbolAddress((void**)&h1lo, g_h1lo);
    cudaGetSymbolAddress((void**)&h2hi, g_h2hi);
    cudaGetSymbolAddress((void**)&h2lo, g_h2lo);
    cudaGetSymbolAddress((void**)&w1h, g_w1thi);
    cudaGetSymbolAddress((void**)&w1l, g_w1tlo);
    cudaGetSymbolAddress((void**)&w2h, g_w2thi);
    cudaGetSymbolAddress((void**)&w2l, g_w2tlo);
    cudaGetSymbolAddress((void**)&w3h, g_w3thi);
    cudaGetSymbolAddress((void**)&w3l, g_w3tlo);
    cudaGetSymbolAddress((void**)&h3, g_h3);

    const int conv_smem = CONV_SMEM_FLOATS * (int)sizeof(float);
    cudaFuncSetAttribute(conv_kernel, cudaFuncAttributeMaxDynamicSharedMemorySize,
                         conv_smem);
    cudaFuncSetAttribute(mma_gemm<true>,
                         cudaFuncAttributeMaxDynamicSharedMemorySize, GEMM_SMEM);
    cudaFuncSetAttribute(mma_gemm<false>,
                         cudaFuncAttributeMaxDynamicSharedMemorySize, GEMM_SMEM);

    // weight prep (cheap, runs while conv occupies the rest of the stream order)
    prep_w<<<dim3(47, 96), dim3(32, 8)>>>(W1, 3065, 1500, 3072, w1h, w1l);
    prep_w<<<dim3(25, 47), dim3(32, 8)>>>(W2, 1500, 800, 1536, w2h, w2l);
    prep_w<<<dim3(4, 25), dim3(32, 8)>>>(W3, 800, 100, 896, w3h, w3l);

    conv_kernel<<<NB, 256, conv_smem>>>(meteo, x_train, cw[0], cb[0], cw[1], cb[1],
                                        cw[2], cb[2], cw[3], cb[3], cw[4], cb[4],
                                        cw[5], cb[5]);

    // L1: 4096 x 1500, Kpad = 3072
    mma_gemm<true><<<dim3(12, 32), 256, GEMM_SMEM>>>(
        h0hi, h0lo, w1h, w1l, b1, 1500, 3072, h1hi, h1lo, nullptr, 1536);
    // L2: 4096 x 800, Kpad = 1536
    mma_gemm<true><<<dim3(7, 32), 256, GEMM_SMEM>>>(
        h1hi, h1lo, w2h, w2l, b2, 800, 1536, h2hi, h2lo, nullptr, 896);
    // L3: 4096 x 100, Kpad = 896
    mma_gemm<false><<<dim3(1, 32), 256, GEMM_SMEM>>>(
        h2hi, h2lo, w3h, w3l, b3, 100, 896, nullptr, nullptr, h3, 100);

    tail_kernel<<<16, 256>>>(h3, W4, b4, xg, Wc, bc, (float*)d_out);
}

// round 5
// speedup vs baseline: 2.2723x; 1.6223x over previous
#include <cuda_runtime.h>
#include <cuda_bf16.h>
#include <cstdint>

#define NB 4096
#define NS 10

// ===========================================================================
// Device scratch (zero-initialized; padding regions never written => stay 0)
// ===========================================================================
__device__ __align__(16) __nv_bfloat16 g_h0hi[NB * 3072];
__device__ __align__(16) __nv_bfloat16 g_h0lo[NB * 3072];
__device__ __align__(16) __nv_bfloat16 g_h1hi[NB * 1536];
__device__ __align__(16) __nv_bfloat16 g_h1lo[NB * 1536];
__device__ __align__(16) __nv_bfloat16 g_h2hi[NB * 896];
__device__ __align__(16) __nv_bfloat16 g_h2lo[NB * 896];
__device__ float g_h3[NB * 100];
// transposed + split weights: [Npad][Kpad]
__device__ __align__(16) __nv_bfloat16 g_w1thi[1536 * 3072];
__device__ __align__(16) __nv_bfloat16 g_w1tlo[1536 * 3072];
__device__ __align__(16) __nv_bfloat16 g_w2thi[896 * 1536];
__device__ __align__(16) __nv_bfloat16 g_w2tlo[896 * 1536];
__device__ __align__(16) __nv_bfloat16 g_w3thi[128 * 896];
__device__ __align__(16) __nv_bfloat16 g_w3tlo[128 * 896];

__device__ __forceinline__ uint32_t smem_u32_of(const void* p) {
    uint32_t a;
    asm("{ .reg .u64 t; cvta.to.shared.u64 t, %1; cvt.u32.u64 %0, t; }"
        : "=r"(a) : "l"(p));
    return a;
}

__device__ __forceinline__ void split_bf16(float v, __nv_bfloat16& hi, __nv_bfloat16& lo) {
    hi = __float2bfloat16(v);
    lo = __float2bfloat16(v - __bfloat162float(hi));
}

// ===========================================================================
// Conv stack v2: t-contiguous layout [s][c][t], rows padded to LP=NCH*8+8
// with zero halo. Window loaded as 4 x LDS128, shared across a co-group.
// ===========================================================================
__device__ __forceinline__ void copy_smem(float* dst, const float* __restrict__ src,
                                          int n, int tid) {
    for (int i = tid; i < n; i += 256) dst[i] = src[i];
}

// conv layer: in rows (s*CIN+ci)*LP, out rows (s*COUT+co)*LP, same L.
template <int CIN, int COUT, int CG, int L>
__device__ __forceinline__ void conv_v2(const float* __restrict__ in,
                                        float* __restrict__ out,
                                        const float* __restrict__ W,
                                        const float* __restrict__ Bias, int tid) {
    constexpr int NCH = (L + 7) / 8;
    constexpr int LP = NCH * 8 + 8;
    constexpr int NG = (COUT + CG - 1) / CG;
    constexpr int ITEMS = NS * NG * NCH;
    for (int it = tid; it < ITEMS; it += 256) {
        int s = it / (NG * NCH);
        int r = it - s * (NG * NCH);
        int g = r / NCH;
        int tc = r - g * NCH;
        int t0 = tc * 8;

        float acc[CG][8];
#pragma unroll
        for (int jc = 0; jc < CG; ++jc) {
            int co = g * CG + jc;
            float bv = (co < COUT) ? Bias[s * COUT + co] : 0.f;
#pragma unroll
            for (int j = 0; j < 8; ++j) acc[jc][j] = bv;
        }

#pragma unroll
        for (int ci = 0; ci < CIN; ++ci) {
            const float* row = in + (s * CIN + ci) * LP;
            float4 q0 = *(const float4*)(row + t0 - 4);
            float4 q1 = *(const float4*)(row + t0);
            float4 q2 = *(const float4*)(row + t0 + 4);
            float4 q3 = *(const float4*)(row + t0 + 8);
            float win[16] = {q0.x, q0.y, q0.z, q0.w, q1.x, q1.y, q1.z, q1.w,
                             q2.x, q2.y, q2.z, q2.w, q3.x, q3.y, q3.z, q3.w};
#pragma unroll
            for (int jc = 0; jc < CG; ++jc) {
                int co = g * CG + jc;
                if (co < COUT) {
                    const float* w = &W[((s * COUT + co) * CIN + ci) * 5];
                    float w0 = w[0], w1 = w[1], w2 = w[2], w3 = w[3], w4 = w[4];
#pragma unroll
                    for (int j = 0; j < 8; ++j)
                        acc[jc][j] += w0 * win[j + 2] + w1 * win[j + 3] +
                                      w2 * win[j + 4] + w3 * win[j + 5] +
                                      w4 * win[j + 6];
                }
            }
        }

#pragma unroll
        for (int jc = 0; jc < CG; ++jc) {
            int co = g * CG + jc;
            if (co < COUT) {
                float* orow = out + (s * COUT + co) * LP;
                float v[8];
#pragma unroll
                for (int j = 0; j < 8; ++j)
                    v[j] = (t0 + j < L) ? fmaxf(acc[jc][j], 0.f) : 0.f;
                *(float4*)(orow + t0) = make_float4(v[0], v[1], v[2], v[3]);
                *(float4*)(orow + t0 + 4) = make_float4(v[4], v[5], v[6], v[7]);
                if (tc == NCH - 1) {  // zero tail [NCH*8, LP)
                    *(float4*)(orow + NCH * 8) = make_float4(0.f, 0.f, 0.f, 0.f);
                    *(float4*)(orow + NCH * 8 + 4) = make_float4(0.f, 0.f, 0.f, 0.f);
                }
            }
        }
    }
}

// maxpool k=5 s=2 over rows (s*C+c): LIN -> LOUT, zero-fills output padding
template <int C, int LIN>
__device__ __forceinline__ void pool_v2(const float* __restrict__ in,
                                        float* __restrict__ out, int tid) {
    constexpr int LOUT = (LIN - 5) / 2 + 1;
    constexpr int LPI = ((LIN + 7) / 8) * 8 + 8;
    constexpr int LPO = ((LOUT + 7) / 8) * 8 + 8;
    constexpr int ITEMS = C * NS * LPO;
    for (int idx = tid; idx < ITEMS; idx += 256) {
        int row = idx / LPO;
        int p = idx - row * LPO;
        float v = 0.f;
        if (p < LOUT) {
            const float* base = in + row * LPI + 2 * p;
            v = fmaxf(fmaxf(fmaxf(base[0], base[1]), fmaxf(base[2], base[3])),
                      base[4]);
        }
        out[row * LPO + p] = v;
    }
}

// smem: wb[5060] | guardA[4] | bufA[8960] | guardB[4] | bufB[12400]
#define CONV_SMEM_FLOATS (5060 + 4 + 8960 + 4 + 12400)

__global__ void __launch_bounds__(256) conv_kernel(
    const float* __restrict__ meteo, const float* __restrict__ x_train,
    const float* __restrict__ cw1, const float* __restrict__ cb1,
    const float* __restrict__ cw2, const float* __restrict__ cb2,
    const float* __restrict__ cw3, const float* __restrict__ cb3,
    const float* __restrict__ cw4, const float* __restrict__ cb4,
    const float* __restrict__ cw5, const float* __restrict__ cb5,
    const float* __restrict__ cw6, const float* __restrict__ cb6) {
    extern __shared__ float sm[];
    float* wb = sm;
    float* bufA = sm + 5060 + 4;
    float* bufB = bufA + 8960 + 4;
    int b = blockIdx.x;
    int tid = threadIdx.x;

    // zero the two 4-float guards (read by row-0 window loads at t0=0)
    if (tid < 4) bufA[-4 + tid] = 0.f;
    else if (tid < 8) bufB[-8 + tid] = 0.f;

    // input transpose: meteo[b][t][s] -> bufB rows [s][t], LP=248, zero pad
    for (int i = tid; i < 10 * 248; i += 256) {
        int s = i / 248, t = i - s * 248;
        bufB[i] = (t < 237) ? meteo[b * 2370 + t * 10 + s] : 0.f;
    }
    copy_smem(wb, cw1, 150, tid);
    copy_smem(wb + 150, cb1, 30, tid);
    __syncthreads();
    conv_v2<1, 3, 3, 237>(bufB, bufA, wb, wb + 150, tid);
    __syncthreads();

    copy_smem(wb, cw2, 750, tid);
    copy_smem(wb + 750, cb2, 50, tid);
    __syncthreads();
    conv_v2<3, 5, 5, 237>(bufA, bufB, wb, wb + 750, tid);
    __syncthreads();

    pool_v2<5, 237>(bufB, bufA, tid);  // -> 5 x 117 (LP 128)
    copy_smem(wb, cw3, 1750, tid);
    copy_smem(wb + 1750, cb3, 70, tid);
    __syncthreads();
    conv_v2<5, 7, 4, 117>(bufA, bufB, wb, wb + 1750, tid);
    __syncthreads();

    copy_smem(wb, cw4, 2450, tid);
    copy_smem(wb + 2450, cb4, 70, tid);
    __syncthreads();
    conv_v2<7, 7, 4, 117>(bufB, bufA, wb, wb + 2450, tid);
    __syncthreads();

    pool_v2<7, 117>(bufA, bufB, tid);  // -> 7 x 57 (LP 72)
    copy_smem(wb, cw5, 3150, tid);
    copy_smem(wb + 3150, cb5, 90, tid);
    __syncthreads();
    conv_v2<7, 9, 3, 57>(bufB, bufA, wb, wb + 3150, tid);
    __syncthreads();

    copy_smem(wb, cw6, 4950, tid);
    copy_smem(wb + 4950, cb6, 110, tid);
    __syncthreads();
    conv_v2<9, 11, 4, 57>(bufA, bufB, wb, wb + 4950, tid);
    __syncthreads();

    // final maxpool (11 x 57 -> 11 x 27) + flatten (co,p,s) + x_train concat
    for (int it = tid; it < 11 * 27 * NS; it += 256) {
        int co = it / (27 * NS);
        int r = it - co * (27 * NS);
        int p = r / NS;
        int s = r - p * NS;
        const float* base = &bufB[(s * 11 + co) * 72 + 2 * p];
        float m = fmaxf(fmaxf(fmaxf(base[0], base[1]), fmaxf(base[2], base[3])),
                        base[4]);
        __nv_bfloat16 hi, lo;
        split_bf16(m, hi, lo);
        g_h0hi[(size_t)b * 3072 + it] = hi;
        g_h0lo[(size_t)b * 3072 + it] = lo;
    }
    for (int i = tid; i < 95; i += 256) {
        __nv_bfloat16 hi, lo;
        split_bf16(x_train[b * 95 + i], hi, lo);
        g_h0hi[(size_t)b * 3072 + 2970 + i] = hi;
        g_h0lo[(size_t)b * 3072 + 2970 + i] = lo;
    }
}

// ===========================================================================
// Weight prep: transpose W[K,N] -> T[n][k] bf16 hi/lo (padding stays zero)
// ===========================================================================
__global__ void __launch_bounds__(256) prep_w(const float* __restrict__ W,
                                              int K, int N, int Kpad,
                                              __nv_bfloat16* __restrict__ Th,
                                              __nv_bfloat16* __restrict__ Tl) {
    __shared__ float sm[32][33];
    int n0 = blockIdx.x * 32, k0 = blockIdx.y * 32;
    int tx = threadIdx.x, ty = threadIdx.y;  // 32 x 8
    for (int i = ty; i < 32; i += 8) {
        int k = k0 + i, n = n0 + tx;
        sm[i][tx] = (k < K && n < N) ? W[(size_t)k * N + n] : 0.f;
    }
    __syncthreads();
    for (int i = ty; i < 32; i += 8) {
        int n = n0 + i, k = k0 + tx;
        if (n < N && k < K) {
            __nv_bfloat16 hi, lo;
            split_bf16(sm[tx][i], hi, lo);
            Th[(size_t)n * Kpad + k] = hi;
            Tl[(size_t)n * Kpad + k] = lo;
        }
    }
}

// ===========================================================================
// bf16 mma.sync GEMM with split-bf16 3-pass accumulation (validated round 4)
// ===========================================================================
#define RS 80
#define TILE_B (128 * RS)
#define STAGE_B (4 * TILE_B)
#define GEMM_SMEM (2 * STAGE_B)

#define CP_ASYNC(s, g) \
    asm volatile("cp.async.cg.shared.global [%0], [%1], 16;" :: "r"(s), "l"(g) : "memory")
#define CP_COMMIT() asm volatile("cp.async.commit_group;" ::: "memory")
#define CP_WAIT(n)  asm volatile("cp.async.wait_group %0;" :: "n"(n) : "memory")

#define LDMX4(r0, r1, r2, r3, a) \
    asm volatile("ldmatrix.sync.aligned.m8n8.x4.shared.b16 {%0,%1,%2,%3}, [%4];" \
                 : "=r"(r0), "=r"(r1), "=r"(r2), "=r"(r3) : "r"(a))

#define MMA(c, a, b) \
    asm volatile("mma.sync.aligned.m16n8k16.row.col.f32.bf16.bf16.f32 " \
                 "{%0,%1,%2,%3}, {%4,%5,%6,%7}, {%8,%9}, {%0,%1,%2,%3};" \
                 : "+f"((c)[0]), "+f"((c)[1]), "+f"((c)[2]), "+f"((c)[3]) \
                 : "r"((a)[0]), "r"((a)[1]), "r"((a)[2]), "r"((a)[3]), \
                   "r"((b)[0]), "r"((b)[1]))

template <bool OUT_BF16>
__global__ void __launch_bounds__(256, 1) mma_gemm(
    const __nv_bfloat16* __restrict__ Ah, const __nv_bfloat16* __restrict__ Al,
    const __nv_bfloat16* __restrict__ Bh, const __nv_bfloat16* __restrict__ Bl,
    const float* __restrict__ bias, int N, int Kpad,
    __nv_bfloat16* __restrict__ Chi, __nv_bfloat16* __restrict__ Clo,
    float* __restrict__ Cf, int ldc) {
    extern __shared__ __align__(16) char smem[];
    uint32_t su = smem_u32_of(smem);

    int tid = threadIdx.x, wid = tid >> 5, lane = tid & 31;
    int warp_m = wid & 1, warp_n = wid >> 1;
    int m0 = blockIdx.y * 128, n0 = blockIdx.x * 128;
    int nkb = Kpad >> 5;

    const __nv_bfloat16* gsrc[4] = {Ah + (size_t)m0 * Kpad, Al + (size_t)m0 * Kpad,
                                    Bh + (size_t)n0 * Kpad, Bl + (size_t)n0 * Kpad};
    int c0 = tid * 2, c1 = tid * 2 + 1;
    int r0c = c0 >> 2, f0 = (c0 & 3) * 8;
    int r1c = c1 >> 2, f1 = (c1 & 3) * 8;

    auto load_stage = [&](int s, int kbe) {
        uint32_t sb = su + s * STAGE_B;
#pragma unroll
        for (int t = 0; t < 4; ++t) {
            const __nv_bfloat16* g = gsrc[t];
            uint32_t tb = sb + t * TILE_B;
            CP_ASYNC(tb + r0c * RS + f0 * 2, g + (size_t)r0c * Kpad + kbe + f0);
            CP_ASYNC(tb + r1c * RS + f1 * 2, g + (size_t)r1c * Kpad + kbe + f1);
        }
        CP_COMMIT();
    };

    int g = lane >> 3, lr = lane & 7;
    uint32_t a_off = (uint32_t)((warp_m * 64 + (g & 1) * 8 + lr) * RS + (g >> 1) * 16);
    uint32_t b_off = (uint32_t)((warp_n * 32 + (g >> 1) * 8 + lr) * RS + (g & 1) * 16);

    float acc[4][4][4];
#pragma unroll
    for (int i = 0; i < 4; i++)
#pragma unroll
        for (int j = 0; j < 4; j++)
#pragma unroll
            for (int e = 0; e < 4; e++) acc[i][j][e] = 0.f;

    load_stage(0, 0);

    for (int kb = 0; kb < nkb; ++kb) {
        if (kb + 1 < nkb) { load_stage((kb + 1) & 1, (kb + 1) * 32); CP_WAIT(1); }
        else              { CP_WAIT(0); }
        __syncthreads();

        uint32_t sb = su + (kb & 1) * STAGE_B;
#pragma unroll
        for (int ks = 0; ks < 2; ++ks) {
            uint32_t ko = ks * 32;
            uint32_t ah[4][4], al[4][4], bh[4][2], bl[4][2];
#pragma unroll
            for (int i = 0; i < 4; ++i) {
                uint32_t ad = sb + a_off + ko + i * (16 * RS);
                LDMX4(ah[i][0], ah[i][1], ah[i][2], ah[i][3], ad);
                LDMX4(al[i][0], al[i][1], al[i][2], al[i][3], ad + TILE_B);
            }
#pragma unroll
            for (int j = 0; j < 4; j += 2) {
                uint32_t bd = sb + 2 * TILE_B + b_off + ko + j * (8 * RS);
                LDMX4(bh[j][0], bh[j][1], bh[j + 1][0], bh[j + 1][1], bd);
                LDMX4(bl[j][0], bl[j][1], bl[j + 1][0], bl[j + 1][1], bd + TILE_B);
            }
#pragma unroll
            for (int i = 0; i < 4; ++i)
#pragma unroll
                for (int j = 0; j < 4; ++j) {
                    MMA(acc[i][j], ah[i], bh[j]);
                    MMA(acc[i][j], ah[i], bl[j]);
                    MMA(acc[i][j], al[i], bh[j]);
                }
        }
        __syncthreads();
    }

    int row_b = m0 + warp_m * 64 + (lane >> 2);
    int col_b = n0 + warp_n * 32 + (lane & 3) * 2;
#pragma unroll
    for (int i = 0; i < 4; ++i)
#pragma unroll
        for (int j = 0; j < 4; ++j) {
            int col = col_b + j * 8;
            if (col < N) {
                float bv0 = bias[col], bv1 = bias[col + 1];
                int r_lo = row_b + i * 16, r_hi = r_lo + 8;
                float v00 = fmaxf(acc[i][j][0] + bv0, 0.f);
                float v01 = fmaxf(acc[i][j][1] + bv1, 0.f);
                float v10 = fmaxf(acc[i][j][2] + bv0, 0.f);
                float v11 = fmaxf(acc[i][j][3] + bv1, 0.f);
                if (OUT_BF16) {
                    __nv_bfloat16 h0, l0, h1, l1;
                    split_bf16(v00, h0, l0); split_bf16(v01, h1, l1);
                    *(__nv_bfloat162*)&Chi[(size_t)r_lo * ldc + col] =
                        __nv_bfloat162(h0, h1);
                    *(__nv_bfloat162*)&Clo[(size_t)r_lo * ldc + col] =
                        __nv_bfloat162(l0, l1);
                    split_bf16(v10, h0, l0); split_bf16(v11, h1, l1);
                    *(__nv_bfloat162*)&Chi[(size_t)r_hi * ldc + col] =
                        __nv_bfloat162(h0, h1);
                    *(__nv_bfloat162*)&Clo[(size_t)r_hi * ldc + col] =
                        __nv_bfloat162(l0, l1);
                } else {
                    Cf[(size_t)r_lo * ldc + col] = v00;
                    Cf[(size_t)r_lo * ldc + col + 1] = v01;
                    Cf[(size_t)r_hi * ldc + col] = v10;
                    Cf[(size_t)r_hi * ldc + col + 1] = v11;
                }
            }
        }
}

// ===========================================================================
// Tail: h4 = relu(h3 @ W4 + b4); out = [h4, xg] @ Wc + bc
// ===========================================================================
__global__ void __launch_bounds__(256) tail_kernel(
    const float* __restrict__ h3, const float* __restrict__ W4,
    const float* __restrict__ b4, const float* __restrict__ xg,
    const float* __restrict__ Wc, const float* __restrict__ bc,
    float* __restrict__ out) {
    __shared__ float w4s[2000];
    __shared__ float b4s[20], wcs[21], bcs[1];
    int tid = threadIdx.x;
    for (int i = tid; i < 2000; i += 256) w4s[i] = W4[i];
    if (tid < 20) b4s[tid] = b4[tid];
    if (tid < 21) wcs[tid] = Wc[tid];
    if (tid == 0) bcs[0] = bc[0];
    __syncthreads();

    int b = blockIdx.x * 256 + tid;
    float acc[20];
#pragma unroll
    for (int j = 0; j < 20; ++j) acc[j] = b4s[j];
    const float* hr = h3 + (size_t)b * 100;
    for (int k = 0; k < 100; ++k) {
        float a = hr[k];
        const float* w = &w4s[k * 20];
#pragma unroll
        for (int j = 0; j < 20; ++j) acc[j] = fmaf(a, w[j], acc[j]);
    }
    float o = bcs[0] + xg[b] * wcs[20];
#pragma unroll
    for (int j = 0; j < 20; ++j) o += fmaxf(acc[j], 0.f) * wcs[j];
    out[b] = o;
}

// ===========================================================================
extern "C" void kernel_launch(void* const* d_in, const int* in_sizes, int n_in,
                              void* d_out, int out_size) {
    const float* x_train = (const float*)d_in[0];
    const float* meteo = (const float*)d_in[1];
    const float* xg = (const float*)d_in[2];
    const float* cw[6];
    const float* cb[6];
    for (int l = 0; l < 6; l++) {
        cw[l] = (const float*)d_in[3 + 2 * l];
        cb[l] = (const float*)d_in[4 + 2 * l];
    }
    const float* W1 = (const float*)d_in[15];
    const float* b1 = (const float*)d_in[16];
    const float* W2 = (const float*)d_in[17];
    const float* b2 = (const float*)d_in[18];
    const float* W3 = (const float*)d_in[19];
    const float* b3 = (const float*)d_in[20];
    const float* W4 = (const float*)d_in[21];
    const float* b4 = (const float*)d_in[22];
    const float* Wc = (const float*)d_in[23];
    const float* bc = (const float*)d_in[24];

    __nv_bfloat16 *h0hi, *h0lo, *h1hi, *h1lo, *h2hi, *h2lo;
    __nv_bfloat16 *w1h, *w1l, *w2h, *w2l, *w3h, *w3l;
    float* h3;
    cudaGetSymbolAddress((void**)&h0hi, g_h0hi);
    cudaGetSymbolAddress((void**)&h0lo, g_h0lo);
    cudaGetSymbolAddress((void**)&h1hi, g_h1hi);
    cudaGetSymbolAddress((void**)&h1lo, g_h1lo);
    cudaGetSymbolAddress((void**)&h2hi, g_h2hi);
    cudaGetSymbolAddress((void**)&h2lo, g_h2lo);
    cudaGetSymbolAddress((void**)&w1h, g_w1thi);
    cudaGetSymbolAddress((void**)&w1l, g_w1tlo);
    cudaGetSymbolAddress((void**)&w2h, g_w2thi);
    cudaGetSymbolAddress((void**)&w2l, g_w2tlo);
    cudaGetSymbolAddress((void**)&w3h, g_w3thi);
    cudaGetSymbolAddress((void**)&w3l, g_w3tlo);
    cudaGetSymbolAddress((void**)&h3, g_h3);

    const int conv_smem = CONV_SMEM_FLOATS * (int)sizeof(float);
    cudaFuncSetAttribute(conv_kernel, cudaFuncAttributeMaxDynamicSharedMemorySize,
                         conv_smem);
    cudaFuncSetAttribute(mma_gemm<true>,
                         cudaFuncAttributeMaxDynamicSharedMemorySize, GEMM_SMEM);
    cudaFuncSetAttribute(mma_gemm<false>,
                         cudaFuncAttributeMaxDynamicSharedMemorySize, GEMM_SMEM);

    prep_w<<<dim3(47, 96), dim3(32, 8)>>>(W1, 3065, 1500, 3072, w1h, w1l);
    prep_w<<<dim3(25, 47), dim3(32, 8)>>>(W2, 1500, 800, 1536, w2h, w2l);
    prep_w<<<dim3(4, 25), dim3(32, 8)>>>(W3, 800, 100, 896, w3h, w3l);

    conv_kernel<<<NB, 256, conv_smem>>>(meteo, x_train, cw[0], cb[0], cw[1], cb[1],
                                        cw[2], cb[2], cw[3], cb[3], cw[4], cb[4],
                                        cw[5], cb[5]);

    // L1: 4096 x 1500, Kpad = 3072
    mma_gemm<true><<<dim3(12, 32), 256, GEMM_SMEM>>>(
        h0hi, h0lo, w1h, w1l, b1, 1500, 3072, h1hi, h1lo, nullptr, 1536);
    // L2: 4096 x 800, Kpad = 1536
    mma_gemm<true><<<dim3(7, 32), 256, GEMM_SMEM>>>(
        h1hi, h1lo, w2h, w2l, b2, 800, 1536, h2hi, h2lo, nullptr, 896);
    // L3: 4096 x 100, Kpad = 896
    mma_gemm<false><<<dim3(1, 32), 256, GEMM_SMEM>>>(
        h2hi, h2lo, w3h, w3l, b3, 100, 896, nullptr, nullptr, h3, 100);

    tail_kernel<<<16, 256>>>(h3, W4, b4, xg, Wc, bc, (float*)d_out);
}

// round 6
// speedup vs baseline: 2.4604x; 1.0828x over previous
#include <cuda_runtime.h>
#include <cuda_bf16.h>
#include <cstdint>

#define NB 4096
#define NS 10
#define CT 320   // conv threads per block

// ===========================================================================
// Device scratch (zero-initialized; padding regions never written => stay 0)
// ===========================================================================
__device__ __align__(16) __nv_bfloat16 g_h0hi[NB * 3072];
__device__ __align__(16) __nv_bfloat16 g_h0lo[NB * 3072];
__device__ __align__(16) __nv_bfloat16 g_h1hi[NB * 1536];
__device__ __align__(16) __nv_bfloat16 g_h1lo[NB * 1536];
__device__ __align__(16) __nv_bfloat16 g_h2hi[NB * 896];
__device__ __align__(16) __nv_bfloat16 g_h2lo[NB * 896];
__device__ float g_h3[NB * 100];
// transposed + split weights: [Npad][Kpad]
__device__ __align__(16) __nv_bfloat16 g_w1thi[1536 * 3072];
__device__ __align__(16) __nv_bfloat16 g_w1tlo[1536 * 3072];
__device__ __align__(16) __nv_bfloat16 g_w2thi[896 * 1536];
__device__ __align__(16) __nv_bfloat16 g_w2tlo[896 * 1536];
__device__ __align__(16) __nv_bfloat16 g_w3thi[128 * 896];
__device__ __align__(16) __nv_bfloat16 g_w3tlo[128 * 896];

__device__ __forceinline__ uint32_t smem_u32_of(const void* p) {
    uint32_t a;
    asm("{ .reg .u64 t; cvta.to.shared.u64 t, %1; cvt.u32.u64 %0, t; }"
        : "=r"(a) : "l"(p));
    return a;
}

__device__ __forceinline__ void split_bf16(float v, __nv_bfloat16& hi, __nv_bfloat16& lo) {
    hi = __float2bfloat16(v);
    lo = __float2bfloat16(v - __bfloat162float(hi));
}

// ===========================================================================
// Conv stack v3: t-contiguous layout [s][c][t], rows padded to LP=NCH*8+8
// with zero halo. 320 threads; CG tuned so every layer is single-iteration.
// ===========================================================================
__device__ __forceinline__ void copy_smem(float* dst, const float* __restrict__ src,
                                          int n, int tid) {
    for (int i = tid; i < n; i += CT) dst[i] = src[i];
}

template <int CIN, int COUT, int CG, int L>
__device__ __forceinline__ void conv_v2(const float* __restrict__ in,
                                        float* __restrict__ out,
                                        const float* __restrict__ W,
                                        const float* __restrict__ Bias, int tid) {
    constexpr int NCH = (L + 7) / 8;
    constexpr int LP = NCH * 8 + 8;
    constexpr int NG = (COUT + CG - 1) / CG;
    constexpr int ITEMS = NS * NG * NCH;
    for (int it = tid; it < ITEMS; it += CT) {
        int s = it / (NG * NCH);
        int r = it - s * (NG * NCH);
        int g = r / NCH;
        int tc = r - g * NCH;
        int t0 = tc * 8;

        float acc[CG][8];
#pragma unroll
        for (int jc = 0; jc < CG; ++jc) {
            int co = g * CG + jc;
            float bv = (co < COUT) ? Bias[s * COUT + co] : 0.f;
#pragma unroll
            for (int j = 0; j < 8; ++j) acc[jc][j] = bv;
        }

#pragma unroll
        for (int ci = 0; ci < CIN; ++ci) {
            const float* row = in + (s * CIN + ci) * LP;
            float4 q0 = *(const float4*)(row + t0 - 4);
            float4 q1 = *(const float4*)(row + t0);
            float4 q2 = *(const float4*)(row + t0 + 4);
            float4 q3 = *(const float4*)(row + t0 + 8);
            float win[16] = {q0.x, q0.y, q0.z, q0.w, q1.x, q1.y, q1.z, q1.w,
                             q2.x, q2.y, q2.z, q2.w, q3.x, q3.y, q3.z, q3.w};
#pragma unroll
            for (int jc = 0; jc < CG; ++jc) {
                int co = g * CG + jc;
                if (co < COUT) {
                    const float* w = &W[((s * COUT + co) * CIN + ci) * 5];
                    float w0 = w[0], w1 = w[1], w2 = w[2], w3 = w[3], w4 = w[4];
#pragma unroll
                    for (int j = 0; j < 8; ++j)
                        acc[jc][j] += w0 * win[j + 2] + w1 * win[j + 3] +
                                      w2 * win[j + 4] + w3 * win[j + 5] +
                                      w4 * win[j + 6];
                }
            }
        }

#pragma unroll
        for (int jc = 0; jc < CG; ++jc) {
            int co = g * CG + jc;
            if (co < COUT) {
                float* orow = out + (s * COUT + co) * LP;
                float v[8];
#pragma unroll
                for (int j = 0; j < 8; ++j)
                    v[j] = (t0 + j < L) ? fmaxf(acc[jc][j], 0.f) : 0.f;
                *(float4*)(orow + t0) = make_float4(v[0], v[1], v[2], v[3]);
                *(float4*)(orow + t0 + 4) = make_float4(v[4], v[5], v[6], v[7]);
                if (tc == NCH - 1) {
                    *(float4*)(orow + NCH * 8) = make_float4(0.f, 0.f, 0.f, 0.f);
                    *(float4*)(orow + NCH * 8 + 4) = make_float4(0.f, 0.f, 0.f, 0.f);
                }
            }
        }
    }
}

template <int C, int LIN>
__device__ __forceinline__ void pool_v2(const float* __restrict__ in,
                                        float* __restrict__ out, int tid) {
    constexpr int LOUT = (LIN - 5) / 2 + 1;
    constexpr int LPI = ((LIN + 7) / 8) * 8 + 8;
    constexpr int LPO = ((LOUT + 7) / 8) * 8 + 8;
    constexpr int ITEMS = C * NS * LPO;
    for (int idx = tid; idx < ITEMS; idx += CT) {
        int row = idx / LPO;
        int p = idx - row * LPO;
        float v = 0.f;
        if (p < LOUT) {
            const float* base = in + row * LPI + 2 * p;
            v = fmaxf(fmaxf(fmaxf(base[0], base[1]), fmaxf(base[2], base[3])),
                      base[4]);
        }
        out[row * LPO + p] = v;
    }
}

// smem: wb[5060] | guardA[4] | bufA[8960] | guardB[4] | bufB[12400]
#define CONV_SMEM_FLOATS (5060 + 4 + 8960 + 4 + 12400)

__global__ void __launch_bounds__(CT, 2) conv_kernel(
    const float* __restrict__ meteo, const float* __restrict__ x_train,
    const float* __restrict__ cw1, const float* __restrict__ cb1,
    const float* __restrict__ cw2, const float* __restrict__ cb2,
    const float* __restrict__ cw3, const float* __restrict__ cb3,
    const float* __restrict__ cw4, const float* __restrict__ cb4,
    const float* __restrict__ cw5, const float* __restrict__ cb5,
    const float* __restrict__ cw6, const float* __restrict__ cb6) {
    extern __shared__ float sm[];
    float* wb = sm;
    float* bufA = sm + 5060 + 4;
    float* bufB = bufA + 8960 + 4;
    int b = blockIdx.x;
    int tid = threadIdx.x;

    if (tid < 4) bufA[-4 + tid] = 0.f;
    else if (tid < 8) bufB[-8 + tid] = 0.f;

    // input transpose: meteo[b][t][s] -> bufB rows [s][t], LP=248, zero pad
    for (int i = tid; i < 10 * 248; i += CT) {
        int s = i / 248, t = i - s * 248;
        bufB[i] = (t < 237) ? meteo[b * 2370 + t * 10 + s] : 0.f;
    }
    copy_smem(wb, cw1, 150, tid);
    copy_smem(wb + 150, cb1, 30, tid);
    __syncthreads();
    conv_v2<1, 3, 3, 237>(bufB, bufA, wb, wb + 150, tid);   // ITEMS=300
    __syncthreads();

    copy_smem(wb, cw2, 750, tid);
    copy_smem(wb + 750, cb2, 50, tid);
    __syncthreads();
    conv_v2<3, 5, 5, 237>(bufA, bufB, wb, wb + 750, tid);   // ITEMS=300
    __syncthreads();

    pool_v2<5, 237>(bufB, bufA, tid);  // -> 5 x 117 (LP 128)
    copy_smem(wb, cw3, 1750, tid);
    copy_smem(wb + 1750, cb3, 70, tid);
    __syncthreads();
    conv_v2<5, 7, 4, 117>(bufA, bufB, wb, wb + 1750, tid);  // ITEMS=300
    __syncthreads();

    copy_smem(wb, cw4, 2450, tid);
    copy_smem(wb + 2450, cb4, 70, tid);
    __syncthreads();
    conv_v2<7, 7, 4, 117>(bufB, bufA, wb, wb + 2450, tid);  // ITEMS=300
    __syncthreads();

    pool_v2<7, 117>(bufA, bufB, tid);  // -> 7 x 57 (LP 72)
    copy_smem(wb, cw5, 3150, tid);
    copy_smem(wb + 3150, cb5, 90, tid);
    __syncthreads();
    conv_v2<7, 9, 3, 57>(bufB, bufA, wb, wb + 3150, tid);   // ITEMS=240
    __syncthreads();

    copy_smem(wb, cw6, 4950, tid);
    copy_smem(wb + 4950, cb6, 110, tid);
    __syncthreads();
    conv_v2<9, 11, 3, 57>(bufA, bufB, wb, wb + 4950, tid);  // ITEMS=320
    __syncthreads();

    // final maxpool (11 x 57 -> 11 x 27) + flatten (co,p,s) + x_train concat
    for (int it = tid; it < 11 * 27 * NS; it += CT) {
        int co = it / (27 * NS);
        int r = it - co * (27 * NS);
        int p = r / NS;
        int s = r - p * NS;
        const float* base = &bufB[(s * 11 + co) * 72 + 2 * p];
        float m = fmaxf(fmaxf(fmaxf(base[0], base[1]), fmaxf(base[2], base[3])),
                        base[4]);
        __nv_bfloat16 hi, lo;
        split_bf16(m, hi, lo);
        g_h0hi[(size_t)b * 3072 + it] = hi;
        g_h0lo[(size_t)b * 3072 + it] = lo;
    }
    for (int i = tid; i < 95; i += CT) {
        __nv_bfloat16 hi, lo;
        split_bf16(x_train[b * 95 + i], hi, lo);
        g_h0hi[(size_t)b * 3072 + 2970 + i] = hi;
        g_h0lo[(size_t)b * 3072 + 2970 + i] = lo;
    }
}

// ===========================================================================
// Weight prep: transpose W[K,N] -> T[n][k] bf16 hi/lo (padding stays zero)
// ===========================================================================
__global__ void __launch_bounds__(256) prep_w(const float* __restrict__ W,
                                              int K, int N, int Kpad,
                                              __nv_bfloat16* __restrict__ Th,
                                              __nv_bfloat16* __restrict__ Tl) {
    __shared__ float sm[32][33];
    int n0 = blockIdx.x * 32, k0 = blockIdx.y * 32;
    int tx = threadIdx.x, ty = threadIdx.y;  // 32 x 8
    for (int i = ty; i < 32; i += 8) {
        int k = k0 + i, n = n0 + tx;
        sm[i][tx] = (k < K && n < N) ? W[(size_t)k * N + n] : 0.f;
    }
    __syncthreads();
    for (int i = ty; i < 32; i += 8) {
        int n = n0 + i, k = k0 + tx;
        if (n < N && k < K) {
            __nv_bfloat16 hi, lo;
            split_bf16(sm[tx][i], hi, lo);
            Th[(size_t)n * Kpad + k] = hi;
            Tl[(size_t)n * Kpad + k] = lo;
        }
    }
}

// ===========================================================================
// bf16 mma.sync GEMM with split-bf16 3-pass accumulation (validated round 4)
// ===========================================================================
#define RS 80
#define TILE_B (128 * RS)
#define STAGE_B (4 * TILE_B)
#define GEMM_SMEM (2 * STAGE_B)

#define CP_ASYNC(s, g) \
    asm volatile("cp.async.cg.shared.global [%0], [%1], 16;" :: "r"(s), "l"(g) : "memory")
#define CP_COMMIT() asm volatile("cp.async.commit_group;" ::: "memory")
#define CP_WAIT(n)  asm volatile("cp.async.wait_group %0;" :: "n"(n) : "memory")

#define LDMX4(r0, r1, r2, r3, a) \
    asm volatile("ldmatrix.sync.aligned.m8n8.x4.shared.b16 {%0,%1,%2,%3}, [%4];" \
                 : "=r"(r0), "=r"(r1), "=r"(r2), "=r"(r3) : "r"(a))

#define MMA(c, a, b) \
    asm volatile("mma.sync.aligned.m16n8k16.row.col.f32.bf16.bf16.f32 " \
                 "{%0,%1,%2,%3}, {%4,%5,%6,%7}, {%8,%9}, {%0,%1,%2,%3};" \
                 : "+f"((c)[0]), "+f"((c)[1]), "+f"((c)[2]), "+f"((c)[3]) \
                 : "r"((a)[0]), "r"((a)[1]), "r"((a)[2]), "r"((a)[3]), \
                   "r"((b)[0]), "r"((b)[1]))

template <bool OUT_BF16>
__global__ void __launch_bounds__(256, 1) mma_gemm(
    const __nv_bfloat16* __restrict__ Ah, const __nv_bfloat16* __restrict__ Al,
    const __nv_bfloat16* __restrict__ Bh, const __nv_bfloat16* __restrict__ Bl,
    const float* __restrict__ bias, int N, int Kpad,
    __nv_bfloat16* __restrict__ Chi, __nv_bfloat16* __restrict__ Clo,
    float* __restrict__ Cf, int ldc) {
    extern __shared__ __align__(16) char smem[];
    uint32_t su = smem_u32_of(smem);

    int tid = threadIdx.x, wid = tid >> 5, lane = tid & 31;
    int warp_m = wid & 1, warp_n = wid >> 1;
    int m0 = blockIdx.y * 128, n0 = blockIdx.x * 128;
    int nkb = Kpad >> 5;

    const __nv_bfloat16* gsrc[4] = {Ah + (size_t)m0 * Kpad, Al + (size_t)m0 * Kpad,
                                    Bh + (size_t)n0 * Kpad, Bl + (size_t)n0 * Kpad};
    int c0 = tid * 2, c1 = tid * 2 + 1;
    int r0c = c0 >> 2, f0 = (c0 & 3) * 8;
    int r1c = c1 >> 2, f1 = (c1 & 3) * 8;

    auto load_stage = [&](int s, int kbe) {
        uint32_t sb = su + s * STAGE_B;
#pragma unroll
        for (int t = 0; t < 4; ++t) {
            const __nv_bfloat16* g = gsrc[t];
            uint32_t tb = sb + t * TILE_B;
            CP_ASYNC(tb + r0c * RS + f0 * 2, g + (size_t)r0c * Kpad + kbe + f0);
            CP_ASYNC(tb + r1c * RS + f1 * 2, g + (size_t)r1c * Kpad + kbe + f1);
        }
        CP_COMMIT();
    };

    int g = lane >> 3, lr = lane & 7;
    uint32_t a_off = (uint32_t)((warp_m * 64 + (g & 1) * 8 + lr) * RS + (g >> 1) * 16);
    uint32_t b_off = (uint32_t)((warp_n * 32 + (g >> 1) * 8 + lr) * RS + (g & 1) * 16);

    float acc[4][4][4];
#pragma unroll
    for (int i = 0; i < 4; i++)
#pragma unroll
        for (int j = 0; j < 4; j++)
#pragma unroll
            for (int e = 0; e < 4; e++) acc[i][j][e] = 0.f;

    load_stage(0, 0);

    for (int kb = 0; kb < nkb; ++kb) {
        if (kb + 1 < nkb) { load_stage((kb + 1) & 1, (kb + 1) * 32); CP_WAIT(1); }
        else              { CP_WAIT(0); }
        __syncthreads();

        uint32_t sb = su + (kb & 1) * STAGE_B;
#pragma unroll
        for (int ks = 0; ks < 2; ++ks) {
            uint32_t ko = ks * 32;
            uint32_t ah[4][4], al[4][4], bh[4][2], bl[4][2];
#pragma unroll
            for (int i = 0; i < 4; ++i) {
                uint32_t ad = sb + a_off + ko + i * (16 * RS);
                LDMX4(ah[i][0], ah[i][1], ah[i][2], ah[i][3], ad);
                LDMX4(al[i][0], al[i][1], al[i][2], al[i][3], ad + TILE_B);
            }
#pragma unroll
            for (int j = 0; j < 4; j += 2) {
                uint32_t bd = sb + 2 * TILE_B + b_off + ko + j * (8 * RS);
                LDMX4(bh[j][0], bh[j][1], bh[j + 1][0], bh[j + 1][1], bd);
                LDMX4(bl[j][0], bl[j][1], bl[j + 1][0], bl[j + 1][1], bd + TILE_B);
            }
#pragma unroll
            for (int i = 0; i < 4; ++i)
#pragma unroll
                for (int j = 0; j < 4; ++j) {
                    MMA(acc[i][j], ah[i], bh[j]);
                    MMA(acc[i][j], ah[i], bl[j]);
                    MMA(acc[i][j], al[i], bh[j]);
                }
        }
        __syncthreads();
    }

    int row_b = m0 + warp_m * 64 + (lane >> 2);
    int col_b = n0 + warp_n * 32 + (lane & 3) * 2;
#pragma unroll
    for (int i = 0; i < 4; ++i)
#pragma unroll
        for (int j = 0; j < 4; ++j) {
            int col = col_b + j * 8;
            if (col < N) {
                float bv0 = bias[col], bv1 = bias[col + 1];
                int r_lo = row_b + i * 16, r_hi = r_lo + 8;
                float v00 = fmaxf(acc[i][j][0] + bv0, 0.f);
                float v01 = fmaxf(acc[i][j][1] + bv1, 0.f);
                float v10 = fmaxf(acc[i][j][2] + bv0, 0.f);
                float v11 = fmaxf(acc[i][j][3] + bv1, 0.f);
                if (OUT_BF16) {
                    __nv_bfloat16 h0, l0, h1, l1;
                    split_bf16(v00, h0, l0); split_bf16(v01, h1, l1);
                    *(__nv_bfloat162*)&Chi[(size_t)r_lo * ldc + col] =
                        __nv_bfloat162(h0, h1);
                    *(__nv_bfloat162*)&Clo[(size_t)r_lo * ldc + col] =
                        __nv_bfloat162(l0, l1);
                    split_bf16(v10, h0, l0); split_bf16(v11, h1, l1);
                    *(__nv_bfloat162*)&Chi[(size_t)r_hi * ldc + col] =
                        __nv_bfloat162(h0, h1);
                    *(__nv_bfloat162*)&Clo[(size_t)r_hi * ldc + col] =
                        __nv_bfloat162(l0, l1);
                } else {
                    Cf[(size_t)r_lo * ldc + col] = v00;
                    Cf[(size_t)r_lo * ldc + col + 1] = v01;
                    Cf[(size_t)r_hi * ldc + col] = v10;
                    Cf[(size_t)r_hi * ldc + col + 1] = v11;
                }
            }
        }
}

// ===========================================================================
// Tail: h4 = relu(h3 @ W4 + b4); out = [h4, xg] @ Wc + bc
// ===========================================================================
__global__ void __launch_bounds__(256) tail_kernel(
    const float* __restrict__ h3, const float* __restrict__ W4,
    const float* __restrict__ b4, const float* __restrict__ xg,
    const float* __restrict__ Wc, const float* __restrict__ bc,
    float* __restrict__ out) {
    __shared__ float w4s[2000];
    __shared__ float b4s[20], wcs[21], bcs[1];
    int tid = threadIdx.x;
    for (int i = tid; i < 2000; i += 256) w4s[i] = W4[i];
    if (tid < 20) b4s[tid] = b4[tid];
    if (tid < 21) wcs[tid] = Wc[tid];
    if (tid == 0) bcs[0] = bc[0];
    __syncthreads();

    int b = blockIdx.x * 256 + tid;
    float acc[20];
#pragma unroll
    for (int j = 0; j < 20; ++j) acc[j] = b4s[j];
    const float* hr = h3 + (size_t)b * 100;
    for (int k = 0; k < 100; ++k) {
        float a = hr[k];
        const float* w = &w4s[k * 20];
#pragma unroll
        for (int j = 0; j < 20; ++j) acc[j] = fmaf(a, w[j], acc[j]);
    }
    float o = bcs[0] + xg[b] * wcs[20];
#pragma unroll
    for (int j = 0; j < 20; ++j) o += fmaxf(acc[j], 0.f) * wcs[j];
    out[b] = o;
}

// ===========================================================================
extern "C" void kernel_launch(void* const* d_in, const int* in_sizes, int n_in,
                              void* d_out, int out_size) {
    const float* x_train = (const float*)d_in[0];
    const float* meteo = (const float*)d_in[1];
    const float* xg = (const float*)d_in[2];
    const float* cw[6];
    const float* cb[6];
    for (int l = 0; l < 6; l++) {
        cw[l] = (const float*)d_in[3 + 2 * l];
        cb[l] = (const float*)d_in[4 + 2 * l];
    }
    const float* W1 = (const float*)d_in[15];
    const float* b1 = (const float*)d_in[16];
    const float* W2 = (const float*)d_in[17];
    const float* b2 = (const float*)d_in[18];
    const float* W3 = (const float*)d_in[19];
    const float* b3 = (const float*)d_in[20];
    const float* W4 = (const float*)d_in[21];
    const float* b4 = (const float*)d_in[22];
    const float* Wc = (const float*)d_in[23];
    const float* bc = (const float*)d_in[24];

    __nv_bfloat16 *h0hi, *h0lo, *h1hi, *h1lo, *h2hi, *h2lo;
    __nv_bfloat16 *w1h, *w1l, *w2h, *w2l, *w3h, *w3l;
    float* h3;
    cudaGetSymbolAddress((void**)&h0hi, g_h0hi);
    cudaGetSymbolAddress((void**)&h0lo, g_h0lo);
    cudaGetSymbolAddress((void**)&h1hi, g_h1hi);
    cudaGetSymbolAddress((void**)&h1lo, g_h1lo);
    cudaGetSymbolAddress((void**)&h2hi, g_h2hi);
    cudaGetSymbolAddress((void**)&h2lo, g_h2lo);
    cudaGetSymbolAddress((void**)&w1h, g_w1thi);
    cudaGetSymbolAddress((void**)&w1l, g_w1tlo);
    cudaGetSymbolAddress((void**)&w2h, g_w2thi);
    cudaGetSymbolAddress((void**)&w2l, g_w2tlo);
    cudaGetSymbolAddress((void**)&w3h, g_w3thi);
    cudaGetSymbolAddress((void**)&w3l, g_w3tlo);
    cudaGetSymbolAddress((void**)&h3, g_h3);

    const int conv_smem = CONV_SMEM_FLOATS * (int)sizeof(float);
    cudaFuncSetAttribute(conv_kernel, cudaFuncAttributeMaxDynamicSharedMemorySize,
                         conv_smem);
    cudaFuncSetAttribute(mma_gemm<true>,
                         cudaFuncAttributeMaxDynamicSharedMemorySize, GEMM_SMEM);
    cudaFuncSetAttribute(mma_gemm<false>,
                         cudaFuncAttributeMaxDynamicSharedMemorySize, GEMM_SMEM);

    prep_w<<<dim3(47, 96), dim3(32, 8)>>>(W1, 3065, 1500, 3072, w1h, w1l);
    prep_w<<<dim3(25, 47), dim3(32, 8)>>>(W2, 1500, 800, 1536, w2h, w2l);
    prep_w<<<dim3(4, 25), dim3(32, 8)>>>(W3, 800, 100, 896, w3h, w3l);

    conv_kernel<<<NB, CT, conv_smem>>>(meteo, x_train, cw[0], cb[0], cw[1], cb[1],
                                       cw[2], cb[2], cw[3], cb[3], cw[4], cb[4],
                                       cw[5], cb[5]);

    // L1: 4096 x 1500, Kpad = 3072
    mma_gemm<true><<<dim3(12, 32), 256, GEMM_SMEM>>>(
        h0hi, h0lo, w1h, w1l, b1, 1500, 3072, h1hi, h1lo, nullptr, 1536);
    // L2: 4096 x 800, Kpad = 1536
    mma_gemm<true><<<dim3(7, 32), 256, GEMM_SMEM>>>(
        h1hi, h1lo, w2h, w2l, b2, 800, 1536, h2hi, h2lo, nullptr, 896);
    // L3: 4096 x 100, Kpad = 896
    mma_gemm<false><<<dim3(1, 32), 256, GEMM_SMEM>>>(
        h2hi, h2lo, w3h, w3l, b3, 100, 896, nullptr, nullptr, h3, 100);

    tail_kernel<<<16, 256>>>(h3, W4, b4, xg, Wc, bc, (float*)d_out);
}

// round 7
// speedup vs baseline: 3.0734x; 1.2492x over previous
#include <cuda_runtime.h>
#include <cuda_fp16.h>
#include <cstdint>

#define NB 4096
#define NS 10
#define CT 320   // conv threads per block

// ===========================================================================
// Device scratch (zero-initialized; padding regions never written => stay 0)
// ===========================================================================
__device__ __align__(16) __half g_h0[NB * 3072];   // feat 2970 + x_train 95, pad->3072
__device__ __align__(16) __half g_h1[NB * 1536];   // 1500 pad 1536
__device__ __align__(16) __half g_h2[NB * 896];    // 800 pad 896
__device__ float g_h3[NB * 100];
// transposed + split weights: [Npad][Kpad], fp16 hi/lo
__device__ __align__(16) __half g_w1th[1536 * 3072];
__device__ __align__(16) __half g_w1tl[1536 * 3072];
__device__ __align__(16) __half g_w2th[896 * 1536];
__device__ __align__(16) __half g_w2tl[896 * 1536];
__device__ __align__(16) __half g_w3th[128 * 896];
__device__ __align__(16) __half g_w3tl[128 * 896];

__device__ __forceinline__ uint32_t smem_u32_of(const void* p) {
    uint32_t a;
    asm("{ .reg .u64 t; cvta.to.shared.u64 t, %1; cvt.u32.u64 %0, t; }"
        : "=r"(a) : "l"(p));
    return a;
}

__device__ __forceinline__ void split_fp16(float v, __half& hi, __half& lo) {
    hi = __float2half(v);
    lo = __float2half(v - __half2float(hi));
}

// ===========================================================================
// Conv stack (validated r5/r6): t-contiguous layout [s][c][t], LP=NCH*8+8,
// zero halo, 320 threads, CG tuned for single-iteration layers.
// ===========================================================================
__device__ __forceinline__ void copy_smem(float* dst, const float* __restrict__ src,
                                          int n, int tid) {
    for (int i = tid; i < n; i += CT) dst[i] = src[i];
}

template <int CIN, int COUT, int CG, int L>
__device__ __forceinline__ void conv_v2(const float* __restrict__ in,
                                        float* __restrict__ out,
                                        const float* __restrict__ W,
                                        const float* __restrict__ Bias, int tid) {
    constexpr int NCH = (L + 7) / 8;
    constexpr int LP = NCH * 8 + 8;
    constexpr int NG = (COUT + CG - 1) / CG;
    constexpr int ITEMS = NS * NG * NCH;
    for (int it = tid; it < ITEMS; it += CT) {
        int s = it / (NG * NCH);
        int r = it - s * (NG * NCH);
        int g = r / NCH;
        int tc = r - g * NCH;
        int t0 = tc * 8;

        float acc[CG][8];
#pragma unroll
        for (int jc = 0; jc < CG; ++jc) {
            int co = g * CG + jc;
            float bv = (co < COUT) ? Bias[s * COUT + co] : 0.f;
#pragma unroll
            for (int j = 0; j < 8; ++j) acc[jc][j] = bv;
        }

#pragma unroll
        for (int ci = 0; ci < CIN; ++ci) {
            const float* row = in + (s * CIN + ci) * LP;
            float4 q0 = *(const float4*)(row + t0 - 4);
            float4 q1 = *(const float4*)(row + t0);
            float4 q2 = *(const float4*)(row + t0 + 4);
            float4 q3 = *(const float4*)(row + t0 + 8);
            float win[16] = {q0.x, q0.y, q0.z, q0.w, q1.x, q1.y, q1.z, q1.w,
                             q2.x, q2.y, q2.z, q2.w, q3.x, q3.y, q3.z, q3.w};
#pragma unroll
            for (int jc = 0; jc < CG; ++jc) {
                int co = g * CG + jc;
                if (co < COUT) {
                    const float* w = &W[((s * COUT + co) * CIN + ci) * 5];
                    float w0 = w[0], w1 = w[1], w2 = w[2], w3 = w[3], w4 = w[4];
#pragma unroll
                    for (int j = 0; j < 8; ++j)
                        acc[jc][j] += w0 * win[j + 2] + w1 * win[j + 3] +
                                      w2 * win[j + 4] + w3 * win[j + 5] +
                                      w4 * win[j + 6];
                }
            }
        }

#pragma unroll
        for (int jc = 0; jc < CG; ++jc) {
            int co = g * CG + jc;
            if (co < COUT) {
                float* orow = out + (s * COUT + co) * LP;
                float v[8];
#pragma unroll
                for (int j = 0; j < 8; ++j)
                    v[j] = (t0 + j < L) ? fmaxf(acc[jc][j], 0.f) : 0.f;
                *(float4*)(orow + t0) = make_float4(v[0], v[1], v[2], v[3]);
                *(float4*)(orow + t0 + 4) = make_float4(v[4], v[5], v[6], v[7]);
                if (tc == NCH - 1) {
                    *(float4*)(orow + NCH * 8) = make_float4(0.f, 0.f, 0.f, 0.f);
                    *(float4*)(orow + NCH * 8 + 4) = make_float4(0.f, 0.f, 0.f, 0.f);
                }
            }
        }
    }
}

template <int C, int LIN>
__device__ __forceinline__ void pool_v2(const float* __restrict__ in,
                                        float* __restrict__ out, int tid) {
    constexpr int LOUT = (LIN - 5) / 2 + 1;
    constexpr int LPI = ((LIN + 7) / 8) * 8 + 8;
    constexpr int LPO = ((LOUT + 7) / 8) * 8 + 8;
    constexpr int ITEMS = C * NS * LPO;
    for (int idx = tid; idx < ITEMS; idx += CT) {
        int row = idx / LPO;
        int p = idx - row * LPO;
        float v = 0.f;
        if (p < LOUT) {
            const float* base = in + row * LPI + 2 * p;
            v = fmaxf(fmaxf(fmaxf(base[0], base[1]), fmaxf(base[2], base[3])),
                      base[4]);
        }
        out[row * LPO + p] = v;
    }
}

// smem: wb[5060] | guardA[4] | bufA[8960] | guardB[4] | bufB[12400]
#define CONV_SMEM_FLOATS (5060 + 4 + 8960 + 4 + 12400)

__global__ void __launch_bounds__(CT, 2) conv_kernel(
    const float* __restrict__ meteo, const float* __restrict__ x_train,
    const float* __restrict__ cw1, const float* __restrict__ cb1,
    const float* __restrict__ cw2, const float* __restrict__ cb2,
    const float* __restrict__ cw3, const float* __restrict__ cb3,
    const float* __restrict__ cw4, const float* __restrict__ cb4,
    const float* __restrict__ cw5, const float* __restrict__ cb5,
    const float* __restrict__ cw6, const float* __restrict__ cb6) {
    extern __shared__ float sm[];
    float* wb = sm;
    float* bufA = sm + 5060 + 4;
    float* bufB = bufA + 8960 + 4;
    int b = blockIdx.x;
    int tid = threadIdx.x;

    if (tid < 4) bufA[-4 + tid] = 0.f;
    else if (tid < 8) bufB[-8 + tid] = 0.f;

    for (int i = tid; i < 10 * 248; i += CT) {
        int s = i / 248, t = i - s * 248;
        bufB[i] = (t < 237) ? meteo[b * 2370 + t * 10 + s] : 0.f;
    }
    copy_smem(wb, cw1, 150, tid);
    copy_smem(wb + 150, cb1, 30, tid);
    __syncthreads();
    conv_v2<1, 3, 3, 237>(bufB, bufA, wb, wb + 150, tid);
    __syncthreads();

    copy_smem(wb, cw2, 750, tid);
    copy_smem(wb + 750, cb2, 50, tid);
    __syncthreads();
    conv_v2<3, 5, 5, 237>(bufA, bufB, wb, wb + 750, tid);
    __syncthreads();

    pool_v2<5, 237>(bufB, bufA, tid);
    copy_smem(wb, cw3, 1750, tid);
    copy_smem(wb + 1750, cb3, 70, tid);
    __syncthreads();
    conv_v2<5, 7, 4, 117>(bufA, bufB, wb, wb + 1750, tid);
    __syncthreads();

    copy_smem(wb, cw4, 2450, tid);
    copy_smem(wb + 2450, cb4, 70, tid);
    __syncthreads();
    conv_v2<7, 7, 4, 117>(bufB, bufA, wb, wb + 2450, tid);
    __syncthreads();

    pool_v2<7, 117>(bufA, bufB, tid);
    copy_smem(wb, cw5, 3150, tid);
    copy_smem(wb + 3150, cb5, 90, tid);
    __syncthreads();
    conv_v2<7, 9, 3, 57>(bufB, bufA, wb, wb + 3150, tid);
    __syncthreads();

    copy_smem(wb, cw6, 4950, tid);
    copy_smem(wb + 4950, cb6, 110, tid);
    __syncthreads();
    conv_v2<9, 11, 3, 57>(bufA, bufB, wb, wb + 4950, tid);
    __syncthreads();

    // final maxpool (11 x 57 -> 11 x 27) + flatten (co,p,s) -> fp16 h0
    for (int it = tid; it < 11 * 27 * NS; it += CT) {
        int co = it / (27 * NS);
        int r = it - co * (27 * NS);
        int p = r / NS;
        int s = r - p * NS;
        const float* base = &bufB[(s * 11 + co) * 72 + 2 * p];
        float m = fmaxf(fmaxf(fmaxf(base[0], base[1]), fmaxf(base[2], base[3])),
                        base[4]);
        g_h0[(size_t)b * 3072 + it] = __float2half(m);
    }
    for (int i = tid; i < 95; i += CT)
        g_h0[(size_t)b * 3072 + 2970 + i] = __float2half(x_train[b * 95 + i]);
}

// ===========================================================================
// Weight prep: transpose W[K,N] -> T[n][k] fp16 hi/lo (padding stays zero)
// ===========================================================================
__global__ void __launch_bounds__(256) prep_w(const float* __restrict__ W,
                                              int K, int N, int Kpad,
                                              __half* __restrict__ Th,
                                              __half* __restrict__ Tl) {
    __shared__ float sm[32][33];
    int n0 = blockIdx.x * 32, k0 = blockIdx.y * 32;
    int tx = threadIdx.x, ty = threadIdx.y;  // 32 x 8
    for (int i = ty; i < 32; i += 8) {
        int k = k0 + i, n = n0 + tx;
        sm[i][tx] = (k < K && n < N) ? W[(size_t)k * N + n] : 0.f;
    }
    __syncthreads();
    for (int i = ty; i < 32; i += 8) {
        int n = n0 + i, k = k0 + tx;
        if (n < N && k < K) {
            __half hi, lo;
            split_fp16(sm[tx][i], hi, lo);
            Th[(size_t)n * Kpad + k] = hi;
            Tl[(size_t)n * Kpad + k] = lo;
        }
    }
}

// ===========================================================================
// fp16 mma.sync GEMM, 2-pass: D = A*Wh + A*Wl (A single fp16, W split hi/lo)
// CTA 128x128, BK=32, 256 thr (8 warps 2Mx4N), cp.async 2-stage, 3 tiles/stage.
// ===========================================================================
#define RS 80
#define TILE_B (128 * RS)          // 10240
#define STAGE_B (3 * TILE_B)       // 30720: [A|Bh|Bl]
#define GEMM_SMEM (2 * STAGE_B)    // 61440

#define CP_ASYNC(s, g) \
    asm volatile("cp.async.cg.shared.global [%0], [%1], 16;" :: "r"(s), "l"(g) : "memory")
#define CP_COMMIT() asm volatile("cp.async.commit_group;" ::: "memory")
#define CP_WAIT(n)  asm volatile("cp.async.wait_group %0;" :: "n"(n) : "memory")

#define LDMX4(r0, r1, r2, r3, a) \
    asm volatile("ldmatrix.sync.aligned.m8n8.x4.shared.b16 {%0,%1,%2,%3}, [%4];" \
                 : "=r"(r0), "=r"(r1), "=r"(r2), "=r"(r3) : "r"(a))

#define MMAH(c, a, b) \
    asm volatile("mma.sync.aligned.m16n8k16.row.col.f32.f16.f16.f32 " \
                 "{%0,%1,%2,%3}, {%4,%5,%6,%7}, {%8,%9}, {%0,%1,%2,%3};" \
                 : "+f"((c)[0]), "+f"((c)[1]), "+f"((c)[2]), "+f"((c)[3]) \
                 : "r"((a)[0]), "r"((a)[1]), "r"((a)[2]), "r"((a)[3]), \
                   "r"((b)[0]), "r"((b)[1]))

template <bool OUT_HALF>
__global__ void __launch_bounds__(256, 2) mma_gemm(
    const __half* __restrict__ A,
    const __half* __restrict__ Bh, const __half* __restrict__ Bl,
    const float* __restrict__ bias, int N, int Kpad,
    __half* __restrict__ C, float* __restrict__ Cf, int ldc) {
    extern __shared__ __align__(16) char smem[];
    uint32_t su = smem_u32_of(smem);

    int tid = threadIdx.x, wid = tid >> 5, lane = tid & 31;
    int warp_m = wid & 1, warp_n = wid >> 1;
    int m0 = blockIdx.y * 128, n0 = blockIdx.x * 128;
    int nkb = Kpad >> 5;

    const __half* gsrc[3] = {A + (size_t)m0 * Kpad, Bh + (size_t)n0 * Kpad,
                             Bl + (size_t)n0 * Kpad};
    int c0 = tid * 2, c1 = tid * 2 + 1;
    int r0c = c0 >> 2, f0 = (c0 & 3) * 8;
    int r1c = c1 >> 2, f1 = (c1 & 3) * 8;

    auto load_stage = [&](int s, int kbe) {
        uint32_t sb = su + s * STAGE_B;
#pragma unroll
        for (int t = 0; t < 3; ++t) {
            const __half* g = gsrc[t];
            uint32_t tb = sb + t * TILE_B;
            CP_ASYNC(tb + r0c * RS + f0 * 2, g + (size_t)r0c * Kpad + kbe + f0);
            CP_ASYNC(tb + r1c * RS + f1 * 2, g + (size_t)r1c * Kpad + kbe + f1);
        }
        CP_COMMIT();
    };

    int g = lane >> 3, lr = lane & 7;
    uint32_t a_off = (uint32_t)((warp_m * 64 + (g & 1) * 8 + lr) * RS + (g >> 1) * 16);
    uint32_t b_off = (uint32_t)((warp_n * 32 + (g >> 1) * 8 + lr) * RS + (g & 1) * 16);

    float acc[4][4][4];
#pragma unroll
    for (int i = 0; i < 4; i++)
#pragma unroll
        for (int j = 0; j < 4; j++)
#pragma unroll
            for (int e = 0; e < 4; e++) acc[i][j][e] = 0.f;

    load_stage(0, 0);

    for (int kb = 0; kb < nkb; ++kb) {
        if (kb + 1 < nkb) { load_stage((kb + 1) & 1, (kb + 1) * 32); CP_WAIT(1); }
        else              { CP_WAIT(0); }
        __syncthreads();

        uint32_t sb = su + (kb & 1) * STAGE_B;
#pragma unroll
        for (int ks = 0; ks < 2; ++ks) {
            uint32_t ko = ks * 32;
            uint32_t ar[4][4], bh[4][2], bl[4][2];
#pragma unroll
            for (int i = 0; i < 4; ++i) {
                uint32_t ad = sb + a_off + ko + i * (16 * RS);
                LDMX4(ar[i][0], ar[i][1], ar[i][2], ar[i][3], ad);
            }
#pragma unroll
            for (int j = 0; j < 4; j += 2) {
                uint32_t bd = sb + TILE_B + b_off + ko + j * (8 * RS);
                LDMX4(bh[j][0], bh[j][1], bh[j + 1][0], bh[j + 1][1], bd);
                LDMX4(bl[j][0], bl[j][1], bl[j + 1][0], bl[j + 1][1], bd + TILE_B);
            }
#pragma unroll
            for (int i = 0; i < 4; ++i)
#pragma unroll
                for (int j = 0; j < 4; ++j) {
                    MMAH(acc[i][j], ar[i], bh[j]);
                    MMAH(acc[i][j], ar[i], bl[j]);
                }
        }
        __syncthreads();
    }

    int row_b = m0 + warp_m * 64 + (lane >> 2);
    int col_b = n0 + warp_n * 32 + (lane & 3) * 2;
#pragma unroll
    for (int i = 0; i < 4; ++i)
#pragma unroll
        for (int j = 0; j < 4; ++j) {
            int col = col_b + j * 8;
            if (col < N) {
                float bv0 = bias[col], bv1 = bias[col + 1];
                int r_lo = row_b + i * 16, r_hi = r_lo + 8;
                float v00 = fmaxf(acc[i][j][0] + bv0, 0.f);
                float v01 = fmaxf(acc[i][j][1] + bv1, 0.f);
                float v10 = fmaxf(acc[i][j][2] + bv0, 0.f);
                float v11 = fmaxf(acc[i][j][3] + bv1, 0.f);
                if (OUT_HALF) {
                    *(__half2*)&C[(size_t)r_lo * ldc + col] =
                        __halves2half2(__float2half(v00), __float2half(v01));
                    *(__half2*)&C[(size_t)r_hi * ldc + col] =
                        __halves2half2(__float2half(v10), __float2half(v11));
                } else {
                    Cf[(size_t)r_lo * ldc + col] = v00;
                    Cf[(size_t)r_lo * ldc + col + 1] = v01;
                    Cf[(size_t)r_hi * ldc + col] = v10;
                    Cf[(size_t)r_hi * ldc + col + 1] = v11;
                }
            }
        }
}

// ===========================================================================
// Tail: h4 = relu(h3 @ W4 + b4); out = [h4, xg] @ Wc + bc
// ===========================================================================
__global__ void __launch_bounds__(256) tail_kernel(
    const float* __restrict__ h3, const float* __restrict__ W4,
    const float* __restrict__ b4, const float* __restrict__ xg,
    const float* __restrict__ Wc, const float* __restrict__ bc,
    float* __restrict__ out) {
    __shared__ float w4s[2000];
    __shared__ float b4s[20], wcs[21], bcs[1];
    int tid = threadIdx.x;
    for (int i = tid; i < 2000; i += 256) w4s[i] = W4[i];
    if (tid < 20) b4s[tid] = b4[tid];
    if (tid < 21) wcs[tid] = Wc[tid];
    if (tid == 0) bcs[0] = bc[0];
    __syncthreads();

    int b = blockIdx.x * 256 + tid;
    float acc[20];
#pragma unroll
    for (int j = 0; j < 20; ++j) acc[j] = b4s[j];
    const float* hr = h3 + (size_t)b * 100;
    for (int k = 0; k < 100; ++k) {
        float a = hr[k];
        const float* w = &w4s[k * 20];
#pragma unroll
        for (int j = 0; j < 20; ++j) acc[j] = fmaf(a, w[j], acc[j]);
    }
    float o = bcs[0] + xg[b] * wcs[20];
#pragma unroll
    for (int j = 0; j < 20; ++j) o += fmaxf(acc[j], 0.f) * wcs[j];
    out[b] = o;
}

// ===========================================================================
extern "C" void kernel_launch(void* const* d_in, const int* in_sizes, int n_in,
                              void* d_out, int out_size) {
    const float* x_train = (const float*)d_in[0];
    const float* meteo = (const float*)d_in[1];
    const float* xg = (const float*)d_in[2];
    const float* cw[6];
    const float* cb[6];
    for (int l = 0; l < 6; l++) {
        cw[l] = (const float*)d_in[3 + 2 * l];
        cb[l] = (const float*)d_in[4 + 2 * l];
    }
    const float* W1 = (const float*)d_in[15];
    const float* b1 = (const float*)d_in[16];
    const float* W2 = (const float*)d_in[17];
    const float* b2 = (const float*)d_in[18];
    const float* W3 = (const float*)d_in[19];
    const float* b3 = (const float*)d_in[20];
    const float* W4 = (const float*)d_in[21];
    const float* b4 = (const float*)d_in[22];
    const float* Wc = (const float*)d_in[23];
    const float* bc = (const float*)d_in[24];

    __half *h0, *h1, *h2;
    __half *w1h, *w1l, *w2h, *w2l, *w3h, *w3l;
    float* h3;
    cudaGetSymbolAddress((void**)&h0, g_h0);
    cudaGetSymbolAddress((void**)&h1, g_h1);
    cudaGetSymbolAddress((void**)&h2, g_h2);
    cudaGetSymbolAddress((void**)&w1h, g_w1th);
    cudaGetSymbolAddress((void**)&w1l, g_w1tl);
    cudaGetSymbolAddress((void**)&w2h, g_w2th);
    cudaGetSymbolAddress((void**)&w2l, g_w2tl);
    cudaGetSymbolAddress((void**)&w3h, g_w3th);
    cudaGetSymbolAddress((void**)&w3l, g_w3tl);
    cudaGetSymbolAddress((void**)&h3, g_h3);

    const int conv_smem = CONV_SMEM_FLOATS * (int)sizeof(float);
    cudaFuncSetAttribute(conv_kernel, cudaFuncAttributeMaxDynamicSharedMemorySize,
                         conv_smem);
    cudaFuncSetAttribute(mma_gemm<true>,
                         cudaFuncAttributeMaxDynamicSharedMemorySize, GEMM_SMEM);
    cudaFuncSetAttribute(mma_gemm<false>,
                         cudaFuncAttributeMaxDynamicSharedMemorySize, GEMM_SMEM);

    prep_w<<<dim3(47, 96), dim3(32, 8)>>>(W1, 3065, 1500, 3072, w1h, w1l);
    prep_w<<<dim3(25, 47), dim3(32, 8)>>>(W2, 1500, 800, 1536, w2h, w2l);
    prep_w<<<dim3(4, 25), dim3(32, 8)>>>(W3, 800, 100, 896, w3h, w3l);

    conv_kernel<<<NB, CT, conv_smem>>>(meteo, x_train, cw[0], cb[0], cw[1], cb[1],
                                       cw[2], cb[2], cw[3], cb[3], cw[4], cb[4],
                                       cw[5], cb[5]);

    // L1: 4096 x 1500, Kpad = 3072
    mma_gemm<true><<<dim3(12, 32), 256, GEMM_SMEM>>>(
        h0, w1h, w1l, b1, 1500, 3072, h1, nullptr, 1536);
    // L2: 4096 x 800, Kpad = 1536
    mma_gemm<true><<<dim3(7, 32), 256, GEMM_SMEM>>>(
        h1, w2h, w2l, b2, 800, 1536, h2, nullptr, 896);
    // L3: 4096 x 100, Kpad = 896
    mma_gemm<false><<<dim3(1, 32), 256, GEMM_SMEM>>>(
        h2, w3h, w3l, b3, 100, 896, nullptr, h3, 100);

    tail_kernel<<<16, 256>>>(h3, W4, b4, xg, Wc, bc, (float*)d_out);
}

// round 8
// speedup vs baseline: 3.3414x; 1.0872x over previous
#include <cuda_runtime.h>
#include <cuda_fp16.h>
#include <cstdint>

#define NB 4096
#define NS 10
#define CT 320   // conv threads per block

// ===========================================================================
// Device scratch (zero-initialized; padding regions never written => stay 0)
// ===========================================================================
__device__ __align__(16) __half g_h0[NB * 3072];   // feat 2970 + x_train 95, pad->3072
__device__ __align__(16) __half g_h1[NB * 1536];   // 1500 pad 1536
__device__ __align__(16) __half g_h2[NB * 896];    // 800 pad 896
__device__ float g_h3[NB * 100];
// transposed + split weights: [Npad][Kpad], fp16 hi/lo
__device__ __align__(16) __half g_w1th[1536 * 3072];
__device__ __align__(16) __half g_w1tl[1536 * 3072];
__device__ __align__(16) __half g_w2th[896 * 1536];
__device__ __align__(16) __half g_w2tl[896 * 1536];
__device__ __align__(16) __half g_w3th[128 * 896];
__device__ __align__(16) __half g_w3tl[128 * 896];

__device__ __forceinline__ uint32_t smem_u32_of(const void* p) {
    uint32_t a;
    asm("{ .reg .u64 t; cvta.to.shared.u64 t, %1; cvt.u32.u64 %0, t; }"
        : "=r"(a) : "l"(p));
    return a;
}

__device__ __forceinline__ void split_fp16(float v, __half& hi, __half& lo) {
    hi = __float2half(v);
    lo = __float2half(v - __half2float(hi));
}

// ---- packed f32x2 helpers (base sm_100 PTX feature) -----------------------
__device__ __forceinline__ unsigned long long pk2(float x, float y) {
    unsigned long long r;
    asm("mov.b64 %0, {%1, %2};" : "=l"(r) : "f"(x), "f"(y));
    return r;
}
__device__ __forceinline__ void upk2(unsigned long long v, float& x, float& y) {
    asm("mov.b64 {%0, %1}, %2;" : "=f"(x), "=f"(y) : "l"(v));
}
#define FMA2(acc, a, b) \
    asm("fma.rn.f32x2 %0, %1, %2, %0;" : "+l"(acc) : "l"(a), "l"(b))

// ===========================================================================
// Conv stack v4: t-contiguous layout [s][c][t], LP=NCH*8+8, zero halo,
// f32x2 packed FMA, weights read directly from global (broadcast L1 hits).
// ===========================================================================
template <int CIN, int COUT, int CG, int L>
__device__ __forceinline__ void conv_v2(const float* __restrict__ in,
                                        float* __restrict__ out,
                                        const float* __restrict__ W,
                                        const float* __restrict__ Bias, int tid) {
    constexpr int NCH = (L + 7) / 8;
    constexpr int LP = NCH * 8 + 8;
    constexpr int NG = (COUT + CG - 1) / CG;
    constexpr int ITEMS = NS * NG * NCH;
    for (int it = tid; it < ITEMS; it += CT) {
        int s = it / (NG * NCH);
        int r = it - s * (NG * NCH);
        int g = r / NCH;
        int tc = r - g * NCH;
        int t0 = tc * 8;

        unsigned long long acc2[CG][4];
#pragma unroll
        for (int jc = 0; jc < CG; ++jc) {
            int co = g * CG + jc;
            float bv = (co < COUT) ? Bias[s * COUT + co] : 0.f;
            unsigned long long bb = pk2(bv, bv);
#pragma unroll
            for (int p = 0; p < 4; ++p) acc2[jc][p] = bb;
        }

#pragma unroll
        for (int ci = 0; ci < CIN; ++ci) {
            const float* row = in + (s * CIN + ci) * LP;
            float4 q0 = *(const float4*)(row + t0 - 4);
            float4 q1 = *(const float4*)(row + t0);
            float4 q2 = *(const float4*)(row + t0 + 4);
            float4 q3 = *(const float4*)(row + t0 + 8);
            float win[16] = {q0.x, q0.y, q0.z, q0.w, q1.x, q1.y, q1.z, q1.w,
                             q2.x, q2.y, q2.z, q2.w, q3.x, q3.y, q3.z, q3.w};
            // distinct adjacent pairs {win[m], win[m+1]}, m in [2, 12]
            unsigned long long P[13];
#pragma unroll
            for (int m = 2; m <= 12; ++m) P[m] = pk2(win[m], win[m + 1]);

#pragma unroll
            for (int jc = 0; jc < CG; ++jc) {
                int co = g * CG + jc;
                if (co < COUT) {
                    const float* w = &W[((s * COUT + co) * CIN + ci) * 5];
                    unsigned long long wp[5];
#pragma unroll
                    for (int k = 0; k < 5; ++k) wp[k] = pk2(w[k], w[k]);
#pragma unroll
                    for (int p = 0; p < 4; ++p)
#pragma unroll
                        for (int k = 0; k < 5; ++k)
                            FMA2(acc2[jc][p], P[2 * p + 2 + k], wp[k]);
                }
            }
        }

#pragma unroll
        for (int jc = 0; jc < CG; ++jc) {
            int co = g * CG + jc;
            if (co < COUT) {
                float* orow = out + (s * COUT + co) * LP;
                float v[8];
#pragma unroll
                for (int p = 0; p < 4; ++p) upk2(acc2[jc][p], v[2 * p], v[2 * p + 1]);
#pragma unroll
                for (int j = 0; j < 8; ++j)
                    v[j] = (t0 + j < L) ? fmaxf(v[j], 0.f) : 0.f;
                *(float4*)(orow + t0) = make_float4(v[0], v[1], v[2], v[3]);
                *(float4*)(orow + t0 + 4) = make_float4(v[4], v[5], v[6], v[7]);
                if (tc == NCH - 1) {
                    *(float4*)(orow + NCH * 8) = make_float4(0.f, 0.f, 0.f, 0.f);
                    *(float4*)(orow + NCH * 8 + 4) = make_float4(0.f, 0.f, 0.f, 0.f);
                }
            }
        }
    }
}

template <int C, int LIN>
__device__ __forceinline__ void pool_v2(const float* __restrict__ in,
                                        float* __restrict__ out, int tid) {
    constexpr int LOUT = (LIN - 5) / 2 + 1;
    constexpr int LPI = ((LIN + 7) / 8) * 8 + 8;
    constexpr int LPO = ((LOUT + 7) / 8) * 8 + 8;
    constexpr int ITEMS = C * NS * LPO;
    for (int idx = tid; idx < ITEMS; idx += CT) {
        int row = idx / LPO;
        int p = idx - row * LPO;
        float v = 0.f;
        if (p < LOUT) {
            const float* base = in + row * LPI + 2 * p;
            v = fmaxf(fmaxf(fmaxf(base[0], base[1]), fmaxf(base[2], base[3])),
                      base[4]);
        }
        out[row * LPO + p] = v;
    }
}

// smem: guardA[4] | bufA[8960] | guardB[4] | bufB[12400]  (no weight staging)
#define CONV_SMEM_FLOATS (4 + 8960 + 4 + 12400)

__global__ void __launch_bounds__(CT, 2) conv_kernel(
    const float* __restrict__ meteo, const float* __restrict__ x_train,
    const float* __restrict__ cw1, const float* __restrict__ cb1,
    const float* __restrict__ cw2, const float* __restrict__ cb2,
    const float* __restrict__ cw3, const float* __restrict__ cb3,
    const float* __restrict__ cw4, const float* __restrict__ cb4,
    const float* __restrict__ cw5, const float* __restrict__ cb5,
    const float* __restrict__ cw6, const float* __restrict__ cb6) {
    extern __shared__ float sm[];
    float* bufA = sm + 4;
    float* bufB = bufA + 8960 + 4;
    int b = blockIdx.x;
    int tid = threadIdx.x;

    if (tid < 4) bufA[-4 + tid] = 0.f;
    else if (tid < 8) bufB[-8 + tid] = 0.f;

    // input transpose: meteo[b][t][s] -> bufB rows [s][t], LP=248, zero pad
    for (int i = tid; i < 10 * 248; i += CT) {
        int s = i / 248, t = i - s * 248;
        bufB[i] = (t < 237) ? meteo[b * 2370 + t * 10 + s] : 0.f;
    }
    __syncthreads();
    conv_v2<1, 3, 3, 237>(bufB, bufA, cw1, cb1, tid);
    __syncthreads();
    conv_v2<3, 5, 5, 237>(bufA, bufB, cw2, cb2, tid);
    __syncthreads();
    pool_v2<5, 237>(bufB, bufA, tid);  // -> 5 x 117 (LP 128)
    __syncthreads();
    conv_v2<5, 7, 4, 117>(bufA, bufB, cw3, cb3, tid);
    __syncthreads();
    conv_v2<7, 7, 4, 117>(bufB, bufA, cw4, cb4, tid);
    __syncthreads();
    pool_v2<7, 117>(bufA, bufB, tid);  // -> 7 x 57 (LP 72)
    __syncthreads();
    conv_v2<7, 9, 3, 57>(bufB, bufA, cw5, cb5, tid);
    __syncthreads();
    conv_v2<9, 11, 3, 57>(bufA, bufB, cw6, cb6, tid);
    __syncthreads();

    // final maxpool (11 x 57 -> 11 x 27) + flatten (co,p,s) -> fp16 h0
    for (int it = tid; it < 11 * 27 * NS; it += CT) {
        int co = it / (27 * NS);
        int r = it - co * (27 * NS);
        int p = r / NS;
        int s = r - p * NS;
        const float* base = &bufB[(s * 11 + co) * 72 + 2 * p];
        float m = fmaxf(fmaxf(fmaxf(base[0], base[1]), fmaxf(base[2], base[3])),
                        base[4]);
        g_h0[(size_t)b * 3072 + it] = __float2half(m);
    }
    for (int i = tid; i < 95; i += CT)
        g_h0[(size_t)b * 3072 + 2970 + i] = __float2half(x_train[b * 95 + i]);
}

// ===========================================================================
// Weight prep: transpose W[K,N] -> T[n][k] fp16 hi/lo (padding stays zero)
// ===========================================================================
__global__ void __launch_bounds__(256) prep_w(const float* __restrict__ W,
                                              int K, int N, int Kpad,
                                              __half* __restrict__ Th,
                                              __half* __restrict__ Tl) {
    __shared__ float sm[32][33];
    int n0 = blockIdx.x * 32, k0 = blockIdx.y * 32;
    int tx = threadIdx.x, ty = threadIdx.y;  // 32 x 8
    for (int i = ty; i < 32; i += 8) {
        int k = k0 + i, n = n0 + tx;
        sm[i][tx] = (k < K && n < N) ? W[(size_t)k * N + n] : 0.f;
    }
    __syncthreads();
    for (int i = ty; i < 32; i += 8) {
        int n = n0 + i, k = k0 + tx;
        if (n < N && k < K) {
            __half hi, lo;
            split_fp16(sm[tx][i], hi, lo);
            Th[(size_t)n * Kpad + k] = hi;
            Tl[(size_t)n * Kpad + k] = lo;
        }
    }
}

// ===========================================================================
// fp16 mma.sync GEMM, 2-pass: D = A*Wh + A*Wl (validated round 7)
// ===========================================================================
#define RS 80
#define TILE_B (128 * RS)          // 10240
#define STAGE_B (3 * TILE_B)       // 30720: [A|Bh|Bl]
#define GEMM_SMEM (2 * STAGE_B)    // 61440

#define CP_ASYNC(s, g) \
    asm volatile("cp.async.cg.shared.global [%0], [%1], 16;" :: "r"(s), "l"(g) : "memory")
#define CP_COMMIT() asm volatile("cp.async.commit_group;" ::: "memory")
#define CP_WAIT(n)  asm volatile("cp.async.wait_group %0;" :: "n"(n) : "memory")

#define LDMX4(r0, r1, r2, r3, a) \
    asm volatile("ldmatrix.sync.aligned.m8n8.x4.shared.b16 {%0,%1,%2,%3}, [%4];" \
                 : "=r"(r0), "=r"(r1), "=r"(r2), "=r"(r3) : "r"(a))

#define MMAH(c, a, b) \
    asm volatile("mma.sync.aligned.m16n8k16.row.col.f32.f16.f16.f32 " \
                 "{%0,%1,%2,%3}, {%4,%5,%6,%7}, {%8,%9}, {%0,%1,%2,%3};" \
                 : "+f"((c)[0]), "+f"((c)[1]), "+f"((c)[2]), "+f"((c)[3]) \
                 : "r"((a)[0]), "r"((a)[1]), "r"((a)[2]), "r"((a)[3]), \
                   "r"((b)[0]), "r"((b)[1]))

template <bool OUT_HALF>
__global__ void __launch_bounds__(256, 2) mma_gemm(
    const __half* __restrict__ A,
    const __half* __restrict__ Bh, const __half* __restrict__ Bl,
    const float* __restrict__ bias, int N, int Kpad,
    __half* __restrict__ C, float* __restrict__ Cf, int ldc) {
    extern __shared__ __align__(16) char smem[];
    uint32_t su = smem_u32_of(smem);

    int tid = threadIdx.x, wid = tid >> 5, lane = tid & 31;
    int warp_m = wid & 1, warp_n = wid >> 1;
    int m0 = blockIdx.y * 128, n0 = blockIdx.x * 128;
    int nkb = Kpad >> 5;

    const __half* gsrc[3] = {A + (size_t)m0 * Kpad, Bh + (size_t)n0 * Kpad,
                             Bl + (size_t)n0 * Kpad};
    int c0 = tid * 2, c1 = tid * 2 + 1;
    int r0c = c0 >> 2, f0 = (c0 & 3) * 8;
    int r1c = c1 >> 2, f1 = (c1 & 3) * 8;

    auto load_stage = [&](int s, int kbe) {
        uint32_t sb = su + s * STAGE_B;
#pragma unroll
        for (int t = 0; t < 3; ++t) {
            const __half* g = gsrc[t];
            uint32_t tb = sb + t * TILE_B;
            CP_ASYNC(tb + r0c * RS + f0 * 2, g + (size_t)r0c * Kpad + kbe + f0);
            CP_ASYNC(tb + r1c * RS + f1 * 2, g + (size_t)r1c * Kpad + kbe + f1);
        }
        CP_COMMIT();
    };

    int g = lane >> 3, lr = lane & 7;
    uint32_t a_off = (uint32_t)((warp_m * 64 + (g & 1) * 8 + lr) * RS + (g >> 1) * 16);
    uint32_t b_off = (uint32_t)((warp_n * 32 + (g >> 1) * 8 + lr) * RS + (g & 1) * 16);

    float acc[4][4][4];
#pragma unroll
    for (int i = 0; i < 4; i++)
#pragma unroll
        for (int j = 0; j < 4; j++)
#pragma unroll
            for (int e = 0; e < 4; e++) acc[i][j][e] = 0.f;

    load_stage(0, 0);

    for (int kb = 0; kb < nkb; ++kb) {
        if (kb + 1 < nkb) { load_stage((kb + 1) & 1, (kb + 1) * 32); CP_WAIT(1); }
        else              { CP_WAIT(0); }
        __syncthreads();

        uint32_t sb = su + (kb & 1) * STAGE_B;
#pragma unroll
        for (int ks = 0; ks < 2; ++ks) {
            uint32_t ko = ks * 32;
            uint32_t ar[4][4], bh[4][2], bl[4][2];
#pragma unroll
            for (int i = 0; i < 4; ++i) {
                uint32_t ad = sb + a_off + ko + i * (16 * RS);
                LDMX4(ar[i][0], ar[i][1], ar[i][2], ar[i][3], ad);
            }
#pragma unroll
            for (int j = 0; j < 4; j += 2) {
                uint32_t bd = sb + TILE_B + b_off + ko + j * (8 * RS);
                LDMX4(bh[j][0], bh[j][1], bh[j + 1][0], bh[j + 1][1], bd);
                LDMX4(bl[j][0], bl[j][1], bl[j + 1][0], bl[j + 1][1], bd + TILE_B);
            }
#pragma unroll
            for (int i = 0; i < 4; ++i)
#pragma unroll
                for (int j = 0; j < 4; ++j) {
                    MMAH(acc[i][j], ar[i], bh[j]);
                    MMAH(acc[i][j], ar[i], bl[j]);
                }
        }
        __syncthreads();
    }

    int row_b = m0 + warp_m * 64 + (lane >> 2);
    int col_b = n0 + warp_n * 32 + (lane & 3) * 2;
#pragma unroll
    for (int i = 0; i < 4; ++i)
#pragma unroll
        for (int j = 0; j < 4; ++j) {
            int col = col_b + j * 8;
            if (col < N) {
                float bv0 = bias[col], bv1 = bias[col + 1];
                int r_lo = row_b + i * 16, r_hi = r_lo + 8;
                float v00 = fmaxf(acc[i][j][0] + bv0, 0.f);
                float v01 = fmaxf(acc[i][j][1] + bv1, 0.f);
                float v10 = fmaxf(acc[i][j][2] + bv0, 0.f);
                float v11 = fmaxf(acc[i][j][3] + bv1, 0.f);
                if (OUT_HALF) {
                    *(__half2*)&C[(size_t)r_lo * ldc + col] =
                        __halves2half2(__float2half(v00), __float2half(v01));
                    *(__half2*)&C[(size_t)r_hi * ldc + col] =
                        __halves2half2(__float2half(v10), __float2half(v11));
                } else {
                    Cf[(size_t)r_lo * ldc + col] = v00;
                    Cf[(size_t)r_lo * ldc + col + 1] = v01;
                    Cf[(size_t)r_hi * ldc + col] = v10;
                    Cf[(size_t)r_hi * ldc + col + 1] = v11;
                }
            }
        }
}

// ===========================================================================
// Tail: h4 = relu(h3 @ W4 + b4); out = [h4, xg] @ Wc + bc
// ===========================================================================
__global__ void __launch_bounds__(256) tail_kernel(
    const float* __restrict__ h3, const float* __restrict__ W4,
    const float* __restrict__ b4, const float* __restrict__ xg,
    const float* __restrict__ Wc, const float* __restrict__ bc,
    float* __restrict__ out) {
    __shared__ float w4s[2000];
    __shared__ float b4s[20], wcs[21], bcs[1];
    int tid = threadIdx.x;
    for (int i = tid; i < 2000; i += 256) w4s[i] = W4[i];
    if (tid < 20) b4s[tid] = b4[tid];
    if (tid < 21) wcs[tid] = Wc[tid];
    if (tid == 0) bcs[0] = bc[0];
    __syncthreads();

    int b = blockIdx.x * 256 + tid;
    float acc[20];
#pragma unroll
    for (int j = 0; j < 20; ++j) acc[j] = b4s[j];
    const float* hr = h3 + (size_t)b * 100;
    for (int k = 0; k < 100; ++k) {
        float a = hr[k];
        const float* w = &w4s[k * 20];
#pragma unroll
        for (int j = 0; j < 20; ++j) acc[j] = fmaf(a, w[j], acc[j]);
    }
    float o = bcs[0] + xg[b] * wcs[20];
#pragma unroll
    for (int j = 0; j < 20; ++j) o += fmaxf(acc[j], 0.f) * wcs[j];
    out[b] = o;
}

// ===========================================================================
extern "C" void kernel_launch(void* const* d_in, const int* in_sizes, int n_in,
                              void* d_out, int out_size) {
    const float* x_train = (const float*)d_in[0];
    const float* meteo = (const float*)d_in[1];
    const float* xg = (const float*)d_in[2];
    const float* cw[6];
    const float* cb[6];
    for (int l = 0; l < 6; l++) {
        cw[l] = (const float*)d_in[3 + 2 * l];
        cb[l] = (const float*)d_in[4 + 2 * l];
    }
    const float* W1 = (const float*)d_in[15];
    const float* b1 = (const float*)d_in[16];
    const float* W2 = (const float*)d_in[17];
    const float* b2 = (const float*)d_in[18];
    const float* W3 = (const float*)d_in[19];
    const float* b3 = (const float*)d_in[20];
    const float* W4 = (const float*)d_in[21];
    const float* b4 = (const float*)d_in[22];
    const float* Wc = (const float*)d_in[23];
    const float* bc = (const float*)d_in[24];

    __half *h0, *h1, *h2;
    __half *w1h, *w1l, *w2h, *w2l, *w3h, *w3l;
    float* h3;
    cudaGetSymbolAddress((void**)&h0, g_h0);
    cudaGetSymbolAddress((void**)&h1, g_h1);
    cudaGetSymbolAddress((void**)&h2, g_h2);
    cudaGetSymbolAddress((void**)&w1h, g_w1th);
    cudaGetSymbolAddress((void**)&w1l, g_w1tl);
    cudaGetSymbolAddress((void**)&w2h, g_w2th);
    cudaGetSymbolAddress((void**)&w2l, g_w2tl);
    cudaGetSymbolAddress((void**)&w3h, g_w3th);
    cudaGetSymbolAddress((void**)&w3l, g_w3tl);
    cudaGetSymbolAddress((void**)&h3, g_h3);

    const int conv_smem = CONV_SMEM_FLOATS * (int)sizeof(float);
    cudaFuncSetAttribute(conv_kernel, cudaFuncAttributeMaxDynamicSharedMemorySize,
                         conv_smem);
    cudaFuncSetAttribute(mma_gemm<true>,
                         cudaFuncAttributeMaxDynamicSharedMemorySize, GEMM_SMEM);
    cudaFuncSetAttribute(mma_gemm<false>,
                         cudaFuncAttributeMaxDynamicSharedMemorySize, GEMM_SMEM);

    prep_w<<<dim3(47, 96), dim3(32, 8)>>>(W1, 3065, 1500, 3072, w1h, w1l);
    prep_w<<<dim3(25, 47), dim3(32, 8)>>>(W2, 1500, 800, 1536, w2h, w2l);
    prep_w<<<dim3(4, 25), dim3(32, 8)>>>(W3, 800, 100, 896, w3h, w3l);

    conv_kernel<<<NB, CT, conv_smem>>>(meteo, x_train, cw[0], cb[0], cw[1], cb[1],
                                       cw[2], cb[2], cw[3], cb[3], cw[4], cb[4],
                                       cw[5], cb[5]);

    // L1: 4096 x 1500, Kpad = 3072
    mma_gemm<true><<<dim3(12, 32), 256, GEMM_SMEM>>>(
        h0, w1h, w1l, b1, 1500, 3072, h1, nullptr, 1536);
    // L2: 4096 x 800, Kpad = 1536
    mma_gemm<true><<<dim3(7, 32), 256, GEMM_SMEM>>>(
        h1, w2h, w2l, b2, 800, 1536, h2, nullptr, 896);
    // L3: 4096 x 100, Kpad = 896
    mma_gemm<false><<<dim3(1, 32), 256, GEMM_SMEM>>>(
        h2, w3h, w3l, b3, 100, 896, nullptr, h3, 100);

    tail_kernel<<<16, 256>>>(h3, W4, b4, xg, Wc, bc, (float*)d_out);
}